// round 1
// baseline (speedup 1.0000x reference)
#include <cuda_runtime.h>
#include <cstddef>

// Problem constants
#define BATCH 8
#define SEQ   1024
#define EMB   1024
#define NHEAD 16
#define DHEAD 64
#define E3    3072   // 3*EMB

// Scratch for QKV projection output: [B, S, 3E] fp32 = 96 MB
__device__ float g_qkv[(size_t)BATCH * SEQ * E3];

// ---------------------------------------------------------------------------
// Robust length read: reference uses int64, but jax default-x64-off may yield
// int32. Values are in [1, 1024], so if the buffer is int64 (little-endian),
// every odd int32 word is 0; if int32, all 8 words are >= 1.
// ---------------------------------------------------------------------------
__device__ __forceinline__ int get_len(const int* __restrict__ p, int b) {
    bool is64 = ((p[1] | p[3] | p[5] | p[7]) == 0);
    return is64 ? p[2 * b] : p[b];
}

// ---------------------------------------------------------------------------
// Kernel A: QKV projection GEMM
// C[m, n] = sum_k A[m, k] * W[n, k] + bias[n]
// A = x [8192, 1024], W [3072, 1024], C [8192, 3072]
// 128x128 tile, BK=16, 256 threads, 8x8 microtile, double-buffered smem.
// ---------------------------------------------------------------------------
__global__ __launch_bounds__(256, 2) void qkv_gemm(
    const float* __restrict__ A,
    const float* __restrict__ W,
    const float* __restrict__ bias,
    float* __restrict__ C)
{
    __shared__ float As[2][16][128];
    __shared__ float Bs[2][16][128];

    const int tid = threadIdx.x;
    const int bm = blockIdx.y * 128;
    const int bn = blockIdx.x * 128;

    // loader: each thread loads one float4 from two rows of each operand
    const int lr = tid >> 2;          // 0..63
    const int lk = (tid & 3) << 2;    // 0,4,8,12

    // compute: 16x16 thread grid, 8x8 microtile each
    const int tm = (tid >> 4) << 3;
    const int tn = (tid & 15) << 3;

    float acc[8][8];
#pragma unroll
    for (int i = 0; i < 8; i++)
#pragma unroll
        for (int j = 0; j < 8; j++) acc[i][j] = 0.f;

    const float* Ag0 = A + (size_t)(bm + lr) * 1024 + lk;
    const float* Ag1 = A + (size_t)(bm + lr + 64) * 1024 + lk;
    const float* Wg0 = W + (size_t)(bn + lr) * 1024 + lk;
    const float* Wg1 = W + (size_t)(bn + lr + 64) * 1024 + lk;

    // prologue: load k-tile 0 into buffer 0
    {
        float4 a0 = *(const float4*)Ag0;
        float4 a1 = *(const float4*)Ag1;
        float4 w0 = *(const float4*)Wg0;
        float4 w1 = *(const float4*)Wg1;
        As[0][lk + 0][lr] = a0.x; As[0][lk + 1][lr] = a0.y;
        As[0][lk + 2][lr] = a0.z; As[0][lk + 3][lr] = a0.w;
        As[0][lk + 0][lr + 64] = a1.x; As[0][lk + 1][lr + 64] = a1.y;
        As[0][lk + 2][lr + 64] = a1.z; As[0][lk + 3][lr + 64] = a1.w;
        Bs[0][lk + 0][lr] = w0.x; Bs[0][lk + 1][lr] = w0.y;
        Bs[0][lk + 2][lr] = w0.z; Bs[0][lk + 3][lr] = w0.w;
        Bs[0][lk + 0][lr + 64] = w1.x; Bs[0][lk + 1][lr + 64] = w1.y;
        Bs[0][lk + 2][lr + 64] = w1.z; Bs[0][lk + 3][lr + 64] = w1.w;
    }
    __syncthreads();

    int buf = 0;
#pragma unroll 1
    for (int kt = 0; kt < 64; kt++) {
        float4 na0, na1, nw0, nw1;
        if (kt < 63) {
            int off = (kt + 1) * 16;
            na0 = *(const float4*)(Ag0 + off);
            na1 = *(const float4*)(Ag1 + off);
            nw0 = *(const float4*)(Wg0 + off);
            nw1 = *(const float4*)(Wg1 + off);
        }

#pragma unroll
        for (int k = 0; k < 16; k++) {
            float av[8], bv[8];
            float4 t;
            t = *(const float4*)&As[buf][k][tm];     av[0]=t.x; av[1]=t.y; av[2]=t.z; av[3]=t.w;
            t = *(const float4*)&As[buf][k][tm + 4]; av[4]=t.x; av[5]=t.y; av[6]=t.z; av[7]=t.w;
            t = *(const float4*)&Bs[buf][k][tn];     bv[0]=t.x; bv[1]=t.y; bv[2]=t.z; bv[3]=t.w;
            t = *(const float4*)&Bs[buf][k][tn + 4]; bv[4]=t.x; bv[5]=t.y; bv[6]=t.z; bv[7]=t.w;
#pragma unroll
            for (int i = 0; i < 8; i++)
#pragma unroll
                for (int j = 0; j < 8; j++)
                    acc[i][j] = fmaf(av[i], bv[j], acc[i][j]);
        }

        if (kt < 63) {
            int nb = buf ^ 1;
            As[nb][lk + 0][lr] = na0.x; As[nb][lk + 1][lr] = na0.y;
            As[nb][lk + 2][lr] = na0.z; As[nb][lk + 3][lr] = na0.w;
            As[nb][lk + 0][lr + 64] = na1.x; As[nb][lk + 1][lr + 64] = na1.y;
            As[nb][lk + 2][lr + 64] = na1.z; As[nb][lk + 3][lr + 64] = na1.w;
            Bs[nb][lk + 0][lr] = nw0.x; Bs[nb][lk + 1][lr] = nw0.y;
            Bs[nb][lk + 2][lr] = nw0.z; Bs[nb][lk + 3][lr] = nw0.w;
            Bs[nb][lk + 0][lr + 64] = nw1.x; Bs[nb][lk + 1][lr + 64] = nw1.y;
            Bs[nb][lk + 2][lr + 64] = nw1.z; Bs[nb][lk + 3][lr + 64] = nw1.w;
            __syncthreads();
            buf = nb;
        }
    }

    // epilogue: add bias, store
    float4 bb0 = *(const float4*)(bias + bn + tn);
    float4 bb1 = *(const float4*)(bias + bn + tn + 4);
#pragma unroll
    for (int i = 0; i < 8; i++) {
        float* cp = C + (size_t)(bm + tm + i) * E3 + bn + tn;
        float4 o0 = make_float4(acc[i][0] + bb0.x, acc[i][1] + bb0.y,
                                acc[i][2] + bb0.z, acc[i][3] + bb0.w);
        float4 o1 = make_float4(acc[i][4] + bb1.x, acc[i][5] + bb1.y,
                                acc[i][6] + bb1.z, acc[i][7] + bb1.w);
        *(float4*)cp = o0;
        *(float4*)(cp + 4) = o1;
    }
}

// ---------------------------------------------------------------------------
// Kernel B: causal flash attention with valid-length clamp.
// Grid: (S/64, H, B), 64 threads/block. Each thread owns one q row in regs.
// qkv layout per token row (3E): [ q(h,dh) | k(h,dh) | v(h,dh) ]
// scale = 1/sqrt(E) = 1/32, folded into q (exact: power of 2).
// ---------------------------------------------------------------------------
__global__ __launch_bounds__(64) void attn_kernel(
    const float* __restrict__ qkv,
    const int* __restrict__ lens,
    float* __restrict__ out)
{
    __shared__ float Ksm[64][64];
    __shared__ float Vsm[64][64];
    __shared__ float Ssm[64][64];   // [c][tid] -> conflict-free

    const int tid = threadIdx.x;
    const int qt = blockIdx.x;
    const int h  = blockIdx.y;
    const int b  = blockIdx.z;

    const int L  = get_len(lens, b);
    const int qr = qt * 64 + tid;

    float* op = out + ((size_t)b * SEQ + qr) * EMB + h * DHEAD;

    if (qt * 64 >= L) {   // whole q-tile beyond valid length -> zeros
        float4 z = make_float4(0.f, 0.f, 0.f, 0.f);
#pragma unroll
        for (int d = 0; d < 64; d += 4) *(float4*)(op + d) = z;
        return;
    }

    // load this thread's q row, pre-scaled by 1/32
    float q[64];
    {
        const float* qp = qkv + ((size_t)b * SEQ + qr) * E3 + h * DHEAD;
#pragma unroll
        for (int d = 0; d < 64; d += 4) {
            float4 v = *(const float4*)(qp + d);
            q[d + 0] = v.x * 0.03125f; q[d + 1] = v.y * 0.03125f;
            q[d + 2] = v.z * 0.03125f; q[d + 3] = v.w * 0.03125f;
        }
    }

    float o[64];
#pragma unroll
    for (int d = 0; d < 64; d++) o[d] = 0.f;
    float m = -1e30f, lsum = 0.f;

    const int ktmax = min(qt, (L - 1) >> 6);
    const float* kbase = qkv + (size_t)b * SEQ * E3 + EMB + h * DHEAD;      // K section
    // V section is +EMB further within the same token row

#pragma unroll 1
    for (int kt = 0; kt <= ktmax; kt++) {
        // cooperative load of K and V tiles (coalesced: 16 threads per row-chunk)
        const float* kp = kbase + (size_t)kt * 64 * E3;
#pragma unroll
        for (int i = 0; i < 16; i++) {
            int flat = i * 64 + tid;          // 0..1023
            int kr = flat >> 4;
            int c4 = (flat & 15) << 2;
            *(float4*)&Ksm[kr][c4] = *(const float4*)(kp + (size_t)kr * E3 + c4);
            *(float4*)&Vsm[kr][c4] = *(const float4*)(kp + (size_t)kr * E3 + EMB + c4);
        }
        __syncthreads();

        const int climit = qr - kt * 64;      // causal: valid c <= climit
        float tmax = -1e30f;
#pragma unroll 2
        for (int c = 0; c < 64; c++) {
            float s0 = 0.f, s1 = 0.f, s2 = 0.f, s3 = 0.f;
#pragma unroll
            for (int d = 0; d < 64; d += 16) {
                float4 k0 = *(const float4*)&Ksm[c][d];
                float4 k1 = *(const float4*)&Ksm[c][d + 4];
                float4 k2 = *(const float4*)&Ksm[c][d + 8];
                float4 k3 = *(const float4*)&Ksm[c][d + 12];
                s0 = fmaf(q[d + 0], k0.x, s0); s0 = fmaf(q[d + 1], k0.y, s0);
                s0 = fmaf(q[d + 2], k0.z, s0); s0 = fmaf(q[d + 3], k0.w, s0);
                s1 = fmaf(q[d + 4], k1.x, s1); s1 = fmaf(q[d + 5], k1.y, s1);
                s1 = fmaf(q[d + 6], k1.z, s1); s1 = fmaf(q[d + 7], k1.w, s1);
                s2 = fmaf(q[d + 8], k2.x, s2); s2 = fmaf(q[d + 9], k2.y, s2);
                s2 = fmaf(q[d +10], k2.z, s2); s2 = fmaf(q[d +11], k2.w, s2);
                s3 = fmaf(q[d +12], k3.x, s3); s3 = fmaf(q[d +13], k3.y, s3);
                s3 = fmaf(q[d +14], k3.z, s3); s3 = fmaf(q[d +15], k3.w, s3);
            }
            float s = (s0 + s1) + (s2 + s3);
            s = (c <= climit) ? s : -1e30f;
            Ssm[c][tid] = s;
            tmax = fmaxf(tmax, s);
        }

        float nm = fmaxf(m, tmax);
        float corr = __expf(m - nm);
        lsum *= corr;
#pragma unroll
        for (int d = 0; d < 64; d++) o[d] *= corr;

#pragma unroll 2
        for (int c = 0; c < 64; c++) {
            float p = __expf(Ssm[c][tid] - nm);
            lsum += p;
#pragma unroll
            for (int d = 0; d < 64; d += 4) {
                float4 v = *(const float4*)&Vsm[c][d];
                o[d + 0] = fmaf(p, v.x, o[d + 0]);
                o[d + 1] = fmaf(p, v.y, o[d + 1]);
                o[d + 2] = fmaf(p, v.z, o[d + 2]);
                o[d + 3] = fmaf(p, v.w, o[d + 3]);
            }
        }
        m = nm;
        __syncthreads();
    }

    if (qr < L) {
        float inv = 1.0f / lsum;
#pragma unroll
        for (int d = 0; d < 64; d += 4) {
            float4 r = make_float4(o[d] * inv, o[d + 1] * inv,
                                   o[d + 2] * inv, o[d + 3] * inv);
            *(float4*)(op + d) = r;
        }
    } else {
        float4 z = make_float4(0.f, 0.f, 0.f, 0.f);
#pragma unroll
        for (int d = 0; d < 64; d += 4) *(float4*)(op + d) = z;
    }
}

// ---------------------------------------------------------------------------
// Launch
// ---------------------------------------------------------------------------
extern "C" void kernel_launch(void* const* d_in, const int* in_sizes, int n_in,
                              void* d_out, int out_size) {
    // Identify inputs by element count (robust to metadata ordering):
    // x: 8388608, l: 8, W: 3145728, b: 3072
    const float* x = nullptr;
    const int*   l = nullptr;
    const float* W = nullptr;
    const float* bias = nullptr;
    for (int i = 0; i < n_in; i++) {
        switch (in_sizes[i]) {
            case 8388608: x    = (const float*)d_in[i]; break;
            case 8:       l    = (const int*)d_in[i];   break;
            case 3145728: W    = (const float*)d_in[i]; break;
            case 3072:    bias = (const float*)d_in[i]; break;
            default: break;
        }
    }
    float* out = (float*)d_out;

    float* qkv_ptr = nullptr;
    cudaGetSymbolAddress((void**)&qkv_ptr, g_qkv);

    dim3 gg(E3 / 128, (BATCH * SEQ) / 128);   // (24, 64)
    qkv_gemm<<<gg, 256>>>(x, W, bias, qkv_ptr);

    dim3 ga(SEQ / 64, NHEAD, BATCH);          // (16, 16, 8)
    attn_kernel<<<ga, 64>>>(qkv_ptr, l, out);
}

// round 3
// speedup vs baseline: 1.9169x; 1.9169x over previous
#include <cuda_runtime.h>
#include <cstdint>
#include <cstddef>

// Problem constants
#define BATCH 8
#define SEQ   1024
#define EMB   1024
#define NHEAD 16
#define DHEAD 64
#define E3    3072   // 3*EMB

// Scratch for QKV projection output: [B, S, 3E] fp32 = 96 MB
__device__ float g_qkv[(size_t)BATCH * SEQ * E3];

// ---------------------------------------------------------------------------
// Helpers
// ---------------------------------------------------------------------------
__device__ __forceinline__ uint32_t smem_u32(const void* p) {
    uint32_t a;
    asm("{ .reg .u64 t; cvta.to.shared.u64 t, %1; cvt.u32.u64 %0, t; }"
        : "=r"(a) : "l"(p));
    return a;
}

__device__ __forceinline__ void cp16(uint32_t dst, const void* src) {
    asm volatile("cp.async.cg.shared.global [%0], [%1], 16;"
                 :: "r"(dst), "l"(src) : "memory");
}

__device__ __forceinline__ uint32_t f2tf32(float x) {
    uint32_t r;
    asm("cvt.rna.tf32.f32 %0, %1;" : "=r"(r) : "f"(x));
    return r;
}

// mma.sync m16n8k8 tf32: D += A*B, row.col, fp32 accum
__device__ __forceinline__ void mma_tf32(float* d, const uint32_t* a, const uint32_t* b) {
    asm volatile(
        "mma.sync.aligned.m16n8k8.row.col.f32.tf32.tf32.f32 "
        "{%0,%1,%2,%3}, {%4,%5,%6,%7}, {%8,%9}, {%0,%1,%2,%3};"
        : "+f"(d[0]), "+f"(d[1]), "+f"(d[2]), "+f"(d[3])
        : "r"(a[0]), "r"(a[1]), "r"(a[2]), "r"(a[3]),
          "r"(b[0]), "r"(b[1]));
}

// ---------------------------------------------------------------------------
// Robust length read (int64 vs int32 l buffer)
// ---------------------------------------------------------------------------
__device__ __forceinline__ int get_len(const int* __restrict__ p, int b) {
    bool is64 = ((p[1] | p[3] | p[5] | p[7]) == 0);
    return is64 ? p[2 * b] : p[b];
}

// ---------------------------------------------------------------------------
// Kernel A: QKV projection GEMM via mma.sync tf32 (tensor cores, sm_100-safe)
// C[m, n] = sum_k A[m, k] * W[n, k] + bias[n]
// A = x [8192, 1024] (MxK, K-major), W [3072, 1024] (NxK, K-major)
// CTA 128x128, BK=32, 3-stage cp.async pipeline, 8 warps (2x4), warp 64x32.
// ---------------------------------------------------------------------------
#define BM 128
#define BN 128
#define BK 32
#define NK (1024 / BK)    // 32
#define NSTG 3
#define ROWP 36           // floats per smem row (pad 32 -> 36, conflict-free frags)
#define STG_FLOATS (128 * ROWP)
#define SMEM_GEMM_TOTAL (2 * NSTG * STG_FLOATS * 4)   // 110592 bytes

__global__ __launch_bounds__(256) void qkv_gemm_mma(
    const float* __restrict__ A,
    const float* __restrict__ W,
    const float* __restrict__ bias,
    float* __restrict__ C)
{
    extern __shared__ float sm[];
    float* Asm = sm;                          // [NSTG][128*ROWP]
    float* Bsm = sm + NSTG * STG_FLOATS;      // [NSTG][128*ROWP]

    const int tid  = threadIdx.x;
    const int wid  = tid >> 5;
    const int lane = tid & 31;
    const int g = lane >> 2;      // 0..7
    const int c = lane & 3;       // 0..3
    const int wm = wid >> 2;      // 0..1  (64 rows each)
    const int wn = wid & 3;       // 0..3  (32 cols each)
    const int bm = blockIdx.y * BM;
    const int bn = blockIdx.x * BN;

    float acc[4][4][4];
#pragma unroll
    for (int mi = 0; mi < 4; mi++)
#pragma unroll
        for (int ni = 0; ni < 4; ni++)
#pragma unroll
            for (int r = 0; r < 4; r++) acc[mi][ni][r] = 0.f;

    const uint32_t sA_u = smem_u32(Asm);
    const uint32_t sB_u = smem_u32(Bsm);

    // ---- stage loader: 128 rows x 32 floats each for A and B ----
    // idx = f*256 + tid in [0,1024): row = idx>>3, 16B chunk = idx&7
#define LOAD_STAGE(kt, s)                                                      \
    {                                                                          \
        const int kof = (kt) * BK;                                             \
        const uint32_t dA = sA_u + (s) * (STG_FLOATS * 4);                     \
        const uint32_t dB = sB_u + (s) * (STG_FLOATS * 4);                     \
        _Pragma("unroll")                                                      \
        for (int f = 0; f < 4; f++) {                                          \
            const int idx = f * 256 + tid;                                     \
            const int row = idx >> 3;                                          \
            const int c4  = (idx & 7) << 2;                                    \
            cp16(dA + (row * ROWP + c4) * 4,                                   \
                 A + (size_t)(bm + row) * 1024 + kof + c4);                    \
            cp16(dB + (row * ROWP + c4) * 4,                                   \
                 W + (size_t)(bn + row) * 1024 + kof + c4);                    \
        }                                                                      \
        asm volatile("cp.async.commit_group;" ::: "memory");                   \
    }

    LOAD_STAGE(0, 0);
    LOAD_STAGE(1, 1);

#pragma unroll 1
    for (int kt = 0; kt < NK; kt++) {
        asm volatile("cp.async.wait_group 1;" ::: "memory");
        __syncthreads();

        if (kt + 2 < NK) {
            const int s2 = (kt + 2) % NSTG;
            LOAD_STAGE(kt + 2, s2);
        }

        const int s = kt % NSTG;
        const float* sA = Asm + s * STG_FLOATS;
        const float* sB = Bsm + s * STG_FLOATS;

#pragma unroll
        for (int kk = 0; kk < 4; kk++) {
            const int col0 = kk * 8 + c;
            uint32_t af[4][4], bf[4][2];
#pragma unroll
            for (int mi = 0; mi < 4; mi++) {
                const int r0 = wm * 64 + mi * 16 + g;
                af[mi][0] = f2tf32(sA[r0 * ROWP + col0]);
                af[mi][1] = f2tf32(sA[(r0 + 8) * ROWP + col0]);
                af[mi][2] = f2tf32(sA[r0 * ROWP + col0 + 4]);
                af[mi][3] = f2tf32(sA[(r0 + 8) * ROWP + col0 + 4]);
            }
#pragma unroll
            for (int ni = 0; ni < 4; ni++) {
                const int n0 = wn * 32 + ni * 8 + g;
                bf[ni][0] = f2tf32(sB[n0 * ROWP + col0]);
                bf[ni][1] = f2tf32(sB[n0 * ROWP + col0 + 4]);
            }
#pragma unroll
            for (int mi = 0; mi < 4; mi++)
#pragma unroll
                for (int ni = 0; ni < 4; ni++)
                    mma_tf32(acc[mi][ni], af[mi], bf[ni]);
        }
    }

    // ---- epilogue: bias + store ----
#pragma unroll
    for (int mi = 0; mi < 4; mi++) {
        const int r0 = bm + wm * 64 + mi * 16 + g;
#pragma unroll
        for (int ni = 0; ni < 4; ni++) {
            const int col = bn + wn * 32 + ni * 8 + c * 2;
            const float bx = __ldg(bias + col);
            const float by = __ldg(bias + col + 1);
            float2 v0 = make_float2(acc[mi][ni][0] + bx, acc[mi][ni][1] + by);
            float2 v1 = make_float2(acc[mi][ni][2] + bx, acc[mi][ni][3] + by);
            *(float2*)(C + (size_t)r0 * E3 + col) = v0;
            *(float2*)(C + (size_t)(r0 + 8) * E3 + col) = v1;
        }
    }
}

// ---------------------------------------------------------------------------
// Kernel B: causal flash attention with valid-length clamp (unchanged, proven)
// ---------------------------------------------------------------------------
__global__ __launch_bounds__(64) void attn_kernel(
    const float* __restrict__ qkv,
    const int* __restrict__ lens,
    float* __restrict__ out)
{
    __shared__ float Ksm[64][64];
    __shared__ float Vsm[64][64];
    __shared__ float Ssm[64][64];

    const int tid = threadIdx.x;
    const int qt = blockIdx.x;
    const int h  = blockIdx.y;
    const int b  = blockIdx.z;

    const int L  = get_len(lens, b);
    const int qr = qt * 64 + tid;

    float* op = out + ((size_t)b * SEQ + qr) * EMB + h * DHEAD;

    if (qt * 64 >= L) {
        float4 z = make_float4(0.f, 0.f, 0.f, 0.f);
#pragma unroll
        for (int d = 0; d < 64; d += 4) *(float4*)(op + d) = z;
        return;
    }

    float q[64];
    {
        const float* qp = qkv + ((size_t)b * SEQ + qr) * E3 + h * DHEAD;
#pragma unroll
        for (int d = 0; d < 64; d += 4) {
            float4 v = *(const float4*)(qp + d);
            q[d + 0] = v.x * 0.03125f; q[d + 1] = v.y * 0.03125f;
            q[d + 2] = v.z * 0.03125f; q[d + 3] = v.w * 0.03125f;
        }
    }

    float o[64];
#pragma unroll
    for (int d = 0; d < 64; d++) o[d] = 0.f;
    float m = -1e30f, lsum = 0.f;

    const int ktmax = min(qt, (L - 1) >> 6);
    const float* kbase = qkv + (size_t)b * SEQ * E3 + EMB + h * DHEAD;

#pragma unroll 1
    for (int kt = 0; kt <= ktmax; kt++) {
        const float* kp = kbase + (size_t)kt * 64 * E3;
#pragma unroll
        for (int i = 0; i < 16; i++) {
            int flat = i * 64 + tid;
            int kr = flat >> 4;
            int c4 = (flat & 15) << 2;
            *(float4*)&Ksm[kr][c4] = *(const float4*)(kp + (size_t)kr * E3 + c4);
            *(float4*)&Vsm[kr][c4] = *(const float4*)(kp + (size_t)kr * E3 + EMB + c4);
        }
        __syncthreads();

        const int climit = qr - kt * 64;
        float tmax = -1e30f;
#pragma unroll 2
        for (int c = 0; c < 64; c++) {
            float s0 = 0.f, s1 = 0.f, s2 = 0.f, s3 = 0.f;
#pragma unroll
            for (int d = 0; d < 64; d += 16) {
                float4 k0 = *(const float4*)&Ksm[c][d];
                float4 k1 = *(const float4*)&Ksm[c][d + 4];
                float4 k2 = *(const float4*)&Ksm[c][d + 8];
                float4 k3 = *(const float4*)&Ksm[c][d + 12];
                s0 = fmaf(q[d + 0], k0.x, s0); s0 = fmaf(q[d + 1], k0.y, s0);
                s0 = fmaf(q[d + 2], k0.z, s0); s0 = fmaf(q[d + 3], k0.w, s0);
                s1 = fmaf(q[d + 4], k1.x, s1); s1 = fmaf(q[d + 5], k1.y, s1);
                s1 = fmaf(q[d + 6], k1.z, s1); s1 = fmaf(q[d + 7], k1.w, s1);
                s2 = fmaf(q[d + 8], k2.x, s2); s2 = fmaf(q[d + 9], k2.y, s2);
                s2 = fmaf(q[d +10], k2.z, s2); s2 = fmaf(q[d +11], k2.w, s2);
                s3 = fmaf(q[d +12], k3.x, s3); s3 = fmaf(q[d +13], k3.y, s3);
                s3 = fmaf(q[d +14], k3.z, s3); s3 = fmaf(q[d +15], k3.w, s3);
            }
            float s = (s0 + s1) + (s2 + s3);
            s = (c <= climit) ? s : -1e30f;
            Ssm[c][tid] = s;
            tmax = fmaxf(tmax, s);
        }

        float nm = fmaxf(m, tmax);
        float corr = __expf(m - nm);
        lsum *= corr;
#pragma unroll
        for (int d = 0; d < 64; d++) o[d] *= corr;

#pragma unroll 2
        for (int c = 0; c < 64; c++) {
            float p = __expf(Ssm[c][tid] - nm);
            lsum += p;
#pragma unroll
            for (int d = 0; d < 64; d += 4) {
                float4 v = *(const float4*)&Vsm[c][d];
                o[d + 0] = fmaf(p, v.x, o[d + 0]);
                o[d + 1] = fmaf(p, v.y, o[d + 1]);
                o[d + 2] = fmaf(p, v.z, o[d + 2]);
                o[d + 3] = fmaf(p, v.w, o[d + 3]);
            }
        }
        m = nm;
        __syncthreads();
    }

    if (qr < L) {
        float inv = 1.0f / lsum;
#pragma unroll
        for (int d = 0; d < 64; d += 4) {
            float4 r = make_float4(o[d] * inv, o[d + 1] * inv,
                                   o[d + 2] * inv, o[d + 3] * inv);
            *(float4*)(op + d) = r;
        }
    } else {
        float4 z = make_float4(0.f, 0.f, 0.f, 0.f);
#pragma unroll
        for (int d = 0; d < 64; d += 4) *(float4*)(op + d) = z;
    }
}

// ---------------------------------------------------------------------------
// Launch
// ---------------------------------------------------------------------------
extern "C" void kernel_launch(void* const* d_in, const int* in_sizes, int n_in,
                              void* d_out, int out_size) {
    const float* x = nullptr;
    const int*   l = nullptr;
    const float* W = nullptr;
    const float* bias = nullptr;
    for (int i = 0; i < n_in; i++) {
        switch (in_sizes[i]) {
            case 8388608: x    = (const float*)d_in[i]; break;
            case 8:       l    = (const int*)d_in[i];   break;
            case 3145728: W    = (const float*)d_in[i]; break;
            case 3072:    bias = (const float*)d_in[i]; break;
            default: break;
        }
    }
    float* out = (float*)d_out;

    float* qkv_ptr = nullptr;
    cudaGetSymbolAddress((void**)&qkv_ptr, g_qkv);

    static bool attr_set = false;
    if (!attr_set) {
        cudaFuncSetAttribute(qkv_gemm_mma,
                             cudaFuncAttributeMaxDynamicSharedMemorySize,
                             SMEM_GEMM_TOTAL);
        attr_set = true;
    }

    dim3 gg(E3 / BN, (BATCH * SEQ) / BM);     // (24, 64)
    qkv_gemm_mma<<<gg, 256, SMEM_GEMM_TOTAL>>>(x, W, bias, qkv_ptr);

    dim3 ga(SEQ / 64, NHEAD, BATCH);          // (16, 16, 8)
    attn_kernel<<<ga, 64>>>(qkv_ptr, l, out);
}

// round 4
// speedup vs baseline: 3.1269x; 1.6313x over previous
#include <cuda_runtime.h>
#include <cstdint>
#include <cstddef>

// Problem constants
#define BATCH 8
#define SEQ   1024
#define EMB   1024
#define NHEAD 16
#define DHEAD 64
#define E3    3072   // 3*EMB

// Scratch for QKV projection output: [B, S, 3E] fp32 = 96 MB
__device__ float g_qkv[(size_t)BATCH * SEQ * E3];

// ---------------------------------------------------------------------------
// Helpers
// ---------------------------------------------------------------------------
__device__ __forceinline__ uint32_t smem_u32(const void* p) {
    uint32_t a;
    asm("{ .reg .u64 t; cvta.to.shared.u64 t, %1; cvt.u32.u64 %0, t; }"
        : "=r"(a) : "l"(p));
    return a;
}

__device__ __forceinline__ void cp16(uint32_t dst, const void* src) {
    asm volatile("cp.async.cg.shared.global [%0], [%1], 16;"
                 :: "r"(dst), "l"(src) : "memory");
}

__device__ __forceinline__ uint32_t f2tf32(float x) {
    uint32_t r;
    asm("cvt.rna.tf32.f32 %0, %1;" : "=r"(r) : "f"(x));
    return r;
}

// mma.sync m16n8k8 tf32: D += A*B, row.col, fp32 accum
__device__ __forceinline__ void mma_tf32(float* d, const uint32_t* a, const uint32_t* b) {
    asm volatile(
        "mma.sync.aligned.m16n8k8.row.col.f32.tf32.tf32.f32 "
        "{%0,%1,%2,%3}, {%4,%5,%6,%7}, {%8,%9}, {%0,%1,%2,%3};"
        : "+f"(d[0]), "+f"(d[1]), "+f"(d[2]), "+f"(d[3])
        : "r"(a[0]), "r"(a[1]), "r"(a[2]), "r"(a[3]),
          "r"(b[0]), "r"(b[1]));
}

// ---------------------------------------------------------------------------
// Robust length read (int64 vs int32 l buffer)
// ---------------------------------------------------------------------------
__device__ __forceinline__ int get_len(const int* __restrict__ p, int b) {
    bool is64 = ((p[1] | p[3] | p[5] | p[7]) == 0);
    return is64 ? p[2 * b] : p[b];
}

// ---------------------------------------------------------------------------
// Kernel A: QKV projection GEMM via mma.sync tf32 (unchanged from R3, proven)
// ---------------------------------------------------------------------------
#define BM 128
#define BN 128
#define BK 32
#define NK (1024 / BK)    // 32
#define NSTG 3
#define ROWP 36
#define STG_FLOATS (128 * ROWP)
#define SMEM_GEMM_TOTAL (2 * NSTG * STG_FLOATS * 4)   // 110592 bytes

__global__ __launch_bounds__(256) void qkv_gemm_mma(
    const float* __restrict__ A,
    const float* __restrict__ W,
    const float* __restrict__ bias,
    float* __restrict__ C)
{
    extern __shared__ float sm[];
    float* Asm = sm;
    float* Bsm = sm + NSTG * STG_FLOATS;

    const int tid  = threadIdx.x;
    const int wid  = tid >> 5;
    const int lane = tid & 31;
    const int g = lane >> 2;
    const int c = lane & 3;
    const int wm = wid >> 2;
    const int wn = wid & 3;
    const int bm = blockIdx.y * BM;
    const int bn = blockIdx.x * BN;

    float acc[4][4][4];
#pragma unroll
    for (int mi = 0; mi < 4; mi++)
#pragma unroll
        for (int ni = 0; ni < 4; ni++)
#pragma unroll
            for (int r = 0; r < 4; r++) acc[mi][ni][r] = 0.f;

    const uint32_t sA_u = smem_u32(Asm);
    const uint32_t sB_u = smem_u32(Bsm);

#define LOAD_STAGE(kt, s)                                                      \
    {                                                                          \
        const int kof = (kt) * BK;                                             \
        const uint32_t dA = sA_u + (s) * (STG_FLOATS * 4);                     \
        const uint32_t dB = sB_u + (s) * (STG_FLOATS * 4);                     \
        _Pragma("unroll")                                                      \
        for (int f = 0; f < 4; f++) {                                          \
            const int idx = f * 256 + tid;                                     \
            const int row = idx >> 3;                                          \
            const int c4  = (idx & 7) << 2;                                    \
            cp16(dA + (row * ROWP + c4) * 4,                                   \
                 A + (size_t)(bm + row) * 1024 + kof + c4);                    \
            cp16(dB + (row * ROWP + c4) * 4,                                   \
                 W + (size_t)(bn + row) * 1024 + kof + c4);                    \
        }                                                                      \
        asm volatile("cp.async.commit_group;" ::: "memory");                   \
    }

    LOAD_STAGE(0, 0);
    LOAD_STAGE(1, 1);

#pragma unroll 1
    for (int kt = 0; kt < NK; kt++) {
        asm volatile("cp.async.wait_group 1;" ::: "memory");
        __syncthreads();

        if (kt + 2 < NK) {
            const int s2 = (kt + 2) % NSTG;
            LOAD_STAGE(kt + 2, s2);
        }

        const int s = kt % NSTG;
        const float* sA = Asm + s * STG_FLOATS;
        const float* sB = Bsm + s * STG_FLOATS;

#pragma unroll
        for (int kk = 0; kk < 4; kk++) {
            const int col0 = kk * 8 + c;
            uint32_t af[4][4], bf[4][2];
#pragma unroll
            for (int mi = 0; mi < 4; mi++) {
                const int r0 = wm * 64 + mi * 16 + g;
                af[mi][0] = f2tf32(sA[r0 * ROWP + col0]);
                af[mi][1] = f2tf32(sA[(r0 + 8) * ROWP + col0]);
                af[mi][2] = f2tf32(sA[r0 * ROWP + col0 + 4]);
                af[mi][3] = f2tf32(sA[(r0 + 8) * ROWP + col0 + 4]);
            }
#pragma unroll
            for (int ni = 0; ni < 4; ni++) {
                const int n0 = wn * 32 + ni * 8 + g;
                bf[ni][0] = f2tf32(sB[n0 * ROWP + col0]);
                bf[ni][1] = f2tf32(sB[n0 * ROWP + col0 + 4]);
            }
#pragma unroll
            for (int mi = 0; mi < 4; mi++)
#pragma unroll
                for (int ni = 0; ni < 4; ni++)
                    mma_tf32(acc[mi][ni], af[mi], bf[ni]);
        }
    }

#pragma unroll
    for (int mi = 0; mi < 4; mi++) {
        const int r0 = bm + wm * 64 + mi * 16 + g;
#pragma unroll
        for (int ni = 0; ni < 4; ni++) {
            const int col = bn + wn * 32 + ni * 8 + c * 2;
            const float bx = __ldg(bias + col);
            const float by = __ldg(bias + col + 1);
            float2 v0 = make_float2(acc[mi][ni][0] + bx, acc[mi][ni][1] + by);
            float2 v1 = make_float2(acc[mi][ni][2] + bx, acc[mi][ni][3] + by);
            *(float2*)(C + (size_t)r0 * E3 + col) = v0;
            *(float2*)(C + (size_t)(r0 + 8) * E3 + col) = v1;
        }
    }
}

// ---------------------------------------------------------------------------
// Kernel B: flash attention on tensor cores (mma.sync tf32)
// Block: 128 threads (4 warps) handles (b, h, 64-row q tile).
// Warp w owns q rows [w*16, w*16+16). Bc = 64 kv per tile.
// smem (floats): K[2][64*68], V[2][64*68], QP[64*68]  (QP: Q staging, then P)
// ---------------------------------------------------------------------------
#define ATT_T   4352                 // 64*68 floats per tile buffer
#define ATT_SMEM ((size_t)(5 * ATT_T) * 4)   // 87040 bytes

__global__ __launch_bounds__(128) void attn_mma(
    const float* __restrict__ qkv,
    const int* __restrict__ lens,
    float* __restrict__ out)
{
    extern __shared__ float smf[];
    float* QP = smf + 4 * ATT_T;

    const int tid  = threadIdx.x;
    const int wid  = tid >> 5;
    const int lane = tid & 31;
    const int g = lane >> 2;     // 0..7
    const int c = lane & 3;      // 0..3

    const int qt = blockIdx.x;
    const int h  = blockIdx.y;
    const int b  = blockIdx.z;
    const int L  = get_len(lens, b);
    const int qbase = qt * 64;

    float* outp = out + ((size_t)(b * SEQ + qbase)) * EMB + h * DHEAD;

    if (qbase >= L) {   // fully masked q tile -> zeros
        float4 z = make_float4(0.f, 0.f, 0.f, 0.f);
#pragma unroll
        for (int t = 0; t < 8; t++) {
            int idx = t * 128 + tid;
            int row = idx >> 4, c4 = (idx & 15) << 2;
            *(float4*)(outp + (size_t)row * EMB + c4) = z;
        }
        return;
    }

    // ---- load Q tile into QP (coalesced) and build scaled Q fragments ----
    {
        const float* qgp = qkv + ((size_t)(b * SEQ + qbase)) * E3 + h * DHEAD;
#pragma unroll
        for (int t = 0; t < 8; t++) {
            int idx = t * 128 + tid;
            int row = idx >> 4, c4 = (idx & 15) << 2;
            *(float4*)&QP[row * 68 + c4] = *(const float4*)(qgp + (size_t)row * E3 + c4);
        }
    }
    __syncthreads();

    uint32_t qf[8][4];
    {
        const int r0 = wid * 16 + g;
#pragma unroll
        for (int kk = 0; kk < 8; kk++) {
            qf[kk][0] = f2tf32(QP[r0 * 68 + kk * 8 + c] * 0.03125f);
            qf[kk][1] = f2tf32(QP[(r0 + 8) * 68 + kk * 8 + c] * 0.03125f);
            qf[kk][2] = f2tf32(QP[r0 * 68 + kk * 8 + c + 4] * 0.03125f);
            qf[kk][3] = f2tf32(QP[(r0 + 8) * 68 + kk * 8 + c + 4] * 0.03125f);
        }
    }
    // No extra sync needed: warp w only reads/writes QP rows [w*16, w*16+16) from here.

    const uint32_t sm_u = smem_u32(smf);
    const int ktmax = min(qt, (L - 1) >> 6);

    // KV tile loader: K at +EMB, V at +2*EMB inside token row
#define KV_LOAD(kt, buf)                                                        \
    {                                                                           \
        const float* kgp = qkv + ((size_t)(b * SEQ + (kt) * 64)) * E3           \
                           + EMB + h * DHEAD;                                   \
        const uint32_t dK = sm_u + (uint32_t)((buf) * ATT_T) * 4;               \
        const uint32_t dV = sm_u + (uint32_t)((2 + (buf)) * ATT_T) * 4;         \
        _Pragma("unroll")                                                       \
        for (int t = 0; t < 8; t++) {                                           \
            int idx = t * 128 + tid;                                            \
            int row = idx >> 4, c4 = (idx & 15) << 2;                           \
            cp16(dK + (row * 68 + c4) * 4, kgp + (size_t)row * E3 + c4);        \
            cp16(dV + (row * 68 + c4) * 4, kgp + (size_t)row * E3 + EMB + c4);  \
        }                                                                       \
        asm volatile("cp.async.commit_group;" ::: "memory");                    \
    }

    KV_LOAD(0, 0);

    float m0 = -1e30f, m1 = -1e30f, l0 = 0.f, l1 = 0.f;
    float oacc[8][4];
#pragma unroll
    for (int dt = 0; dt < 8; dt++)
#pragma unroll
        for (int r = 0; r < 4; r++) oacc[dt][r] = 0.f;

    float* Pw = QP + (wid * 16) * 68;

#pragma unroll 1
    for (int kt = 0; kt <= ktmax; kt++) {
        if (kt < ktmax) KV_LOAD(kt + 1, (kt + 1) & 1);
        if (kt < ktmax) asm volatile("cp.async.wait_group 1;" ::: "memory");
        else            asm volatile("cp.async.wait_group 0;" ::: "memory");
        __syncthreads();

        const float* Kp = smf + (kt & 1) * ATT_T;
        const float* Vp = smf + (2 + (kt & 1)) * ATT_T;

        // ---- S = Q @ K^T ----
        float sacc[8][4];
#pragma unroll
        for (int nt = 0; nt < 8; nt++)
#pragma unroll
            for (int r = 0; r < 4; r++) sacc[nt][r] = 0.f;

#pragma unroll
        for (int kk = 0; kk < 8; kk++) {
#pragma unroll
            for (int nt = 0; nt < 8; nt++) {
                uint32_t bf[2];
                bf[0] = f2tf32(Kp[(nt * 8 + g) * 68 + kk * 8 + c]);
                bf[1] = f2tf32(Kp[(nt * 8 + g) * 68 + kk * 8 + c + 4]);
                mma_tf32(sacc[nt], qf[kk], bf);
            }
        }

        // ---- causal mask (diagonal tile only) ----
        if (kt == qt) {
            const int lr0 = wid * 16 + g;      // local row for regs 0,1
            const int lr1 = lr0 + 8;           // regs 2,3
#pragma unroll
            for (int nt = 0; nt < 8; nt++) {
                const int col0 = nt * 8 + 2 * c;
                if (col0 > lr0)     sacc[nt][0] = -1e30f;
                if (col0 + 1 > lr0) sacc[nt][1] = -1e30f;
                if (col0 > lr1)     sacc[nt][2] = -1e30f;
                if (col0 + 1 > lr1) sacc[nt][3] = -1e30f;
            }
        }

        // ---- online softmax ----
        float tm0 = -1e30f, tm1 = -1e30f;
#pragma unroll
        for (int nt = 0; nt < 8; nt++) {
            tm0 = fmaxf(tm0, fmaxf(sacc[nt][0], sacc[nt][1]));
            tm1 = fmaxf(tm1, fmaxf(sacc[nt][2], sacc[nt][3]));
        }
        tm0 = fmaxf(tm0, __shfl_xor_sync(0xFFFFFFFF, tm0, 1));
        tm0 = fmaxf(tm0, __shfl_xor_sync(0xFFFFFFFF, tm0, 2));
        tm1 = fmaxf(tm1, __shfl_xor_sync(0xFFFFFFFF, tm1, 1));
        tm1 = fmaxf(tm1, __shfl_xor_sync(0xFFFFFFFF, tm1, 2));

        const float nm0 = fmaxf(m0, tm0);
        const float nm1 = fmaxf(m1, tm1);
        const float cor0 = __expf(m0 - nm0);
        const float cor1 = __expf(m1 - nm1);
        l0 *= cor0; l1 *= cor1;
#pragma unroll
        for (int dt = 0; dt < 8; dt++) {
            oacc[dt][0] *= cor0; oacc[dt][1] *= cor0;
            oacc[dt][2] *= cor1; oacc[dt][3] *= cor1;
        }

        float ps0 = 0.f, ps1 = 0.f;
#pragma unroll
        for (int nt = 0; nt < 8; nt++) {
            const float p0 = __expf(sacc[nt][0] - nm0);
            const float p1 = __expf(sacc[nt][1] - nm0);
            const float p2 = __expf(sacc[nt][2] - nm1);
            const float p3 = __expf(sacc[nt][3] - nm1);
            ps0 += p0 + p1; ps1 += p2 + p3;
            Pw[g * 68 + nt * 8 + 2 * c]           = p0;
            Pw[g * 68 + nt * 8 + 2 * c + 1]       = p1;
            Pw[(g + 8) * 68 + nt * 8 + 2 * c]     = p2;
            Pw[(g + 8) * 68 + nt * 8 + 2 * c + 1] = p3;
        }
        ps0 += __shfl_xor_sync(0xFFFFFFFF, ps0, 1);
        ps0 += __shfl_xor_sync(0xFFFFFFFF, ps0, 2);
        ps1 += __shfl_xor_sync(0xFFFFFFFF, ps1, 1);
        ps1 += __shfl_xor_sync(0xFFFFFFFF, ps1, 2);
        l0 += ps0; l1 += ps1;
        m0 = nm0; m1 = nm1;
        __syncwarp();

        // ---- O += P @ V ----
#pragma unroll
        for (int kvc = 0; kvc < 8; kvc++) {
            uint32_t pf[4];
            pf[0] = f2tf32(Pw[g * 68 + kvc * 8 + c]);
            pf[1] = f2tf32(Pw[(g + 8) * 68 + kvc * 8 + c]);
            pf[2] = f2tf32(Pw[g * 68 + kvc * 8 + c + 4]);
            pf[3] = f2tf32(Pw[(g + 8) * 68 + kvc * 8 + c + 4]);
#pragma unroll
            for (int dt = 0; dt < 8; dt++) {
                uint32_t bf[2];
                bf[0] = f2tf32(Vp[(kvc * 8 + c) * 68 + dt * 8 + g]);
                bf[1] = f2tf32(Vp[(kvc * 8 + c + 4) * 68 + dt * 8 + g]);
                mma_tf32(oacc[dt], pf, bf);
            }
        }
        __syncthreads();   // all warps done reading K/V buf before next overwrite
    }

    // ---- epilogue: normalize, predicate rows >= L to zero, store ----
    const float inv0 = 1.0f / l0;
    const float inv1 = 1.0f / l1;
    const int q0row = qbase + wid * 16 + g;
    const int q1row = q0row + 8;
    const bool v0 = (q0row < L);
    const bool v1 = (q1row < L);
    float* o0 = out + ((size_t)(b * SEQ + q0row)) * EMB + h * DHEAD;
    float* o1 = out + ((size_t)(b * SEQ + q1row)) * EMB + h * DHEAD;
#pragma unroll
    for (int dt = 0; dt < 8; dt++) {
        const int col = dt * 8 + 2 * c;
        float2 r0 = v0 ? make_float2(oacc[dt][0] * inv0, oacc[dt][1] * inv0)
                       : make_float2(0.f, 0.f);
        float2 r1 = v1 ? make_float2(oacc[dt][2] * inv1, oacc[dt][3] * inv1)
                       : make_float2(0.f, 0.f);
        *(float2*)(o0 + col) = r0;
        *(float2*)(o1 + col) = r1;
    }
}

// ---------------------------------------------------------------------------
// Launch
// ---------------------------------------------------------------------------
extern "C" void kernel_launch(void* const* d_in, const int* in_sizes, int n_in,
                              void* d_out, int out_size) {
    const float* x = nullptr;
    const int*   l = nullptr;
    const float* W = nullptr;
    const float* bias = nullptr;
    for (int i = 0; i < n_in; i++) {
        switch (in_sizes[i]) {
            case 8388608: x    = (const float*)d_in[i]; break;
            case 8:       l    = (const int*)d_in[i];   break;
            case 3145728: W    = (const float*)d_in[i]; break;
            case 3072:    bias = (const float*)d_in[i]; break;
            default: break;
        }
    }
    float* out = (float*)d_out;

    float* qkv_ptr = nullptr;
    cudaGetSymbolAddress((void**)&qkv_ptr, g_qkv);

    static bool attr_set = false;
    if (!attr_set) {
        cudaFuncSetAttribute(qkv_gemm_mma,
                             cudaFuncAttributeMaxDynamicSharedMemorySize,
                             SMEM_GEMM_TOTAL);
        cudaFuncSetAttribute(attn_mma,
                             cudaFuncAttributeMaxDynamicSharedMemorySize,
                             (int)ATT_SMEM);
        attr_set = true;
    }

    dim3 gg(E3 / BN, (BATCH * SEQ) / BM);     // (24, 64)
    qkv_gemm_mma<<<gg, 256, SMEM_GEMM_TOTAL>>>(x, W, bias, qkv_ptr);

    dim3 ga(SEQ / 64, NHEAD, BATCH);          // (16, 16, 8)
    attn_mma<<<ga, 128, ATT_SMEM>>>(qkv_ptr, l, out);
}

// round 5
// speedup vs baseline: 3.4664x; 1.1086x over previous
#include <cuda_runtime.h>
#include <cstdint>
#include <cstddef>

// Problem constants
#define BATCH 8
#define SEQ   1024
#define EMB   1024
#define NHEAD 16
#define DHEAD 64
#define E3    3072   // 3*EMB

// Scratch: QKV projection output [B,S,3E] fp32 (tf32-rounded values)
__device__ float g_qkv[(size_t)BATCH * SEQ * E3];
// Scratch: tf32-pre-rounded copies of x and W
__device__ float g_xr[(size_t)BATCH * SEQ * EMB];
__device__ float g_wr[(size_t)E3 * EMB];

// ---------------------------------------------------------------------------
// Helpers
// ---------------------------------------------------------------------------
__device__ __forceinline__ uint32_t smem_u32(const void* p) {
    uint32_t a;
    asm("{ .reg .u64 t; cvta.to.shared.u64 t, %1; cvt.u32.u64 %0, t; }"
        : "=r"(a) : "l"(p));
    return a;
}

__device__ __forceinline__ void cp16(uint32_t dst, const void* src) {
    asm volatile("cp.async.cg.shared.global [%0], [%1], 16;"
                 :: "r"(dst), "l"(src) : "memory");
}

__device__ __forceinline__ uint32_t f2tf32(float x) {
    uint32_t r;
    asm("cvt.rna.tf32.f32 %0, %1;" : "=r"(r) : "f"(x));
    return r;
}

// mma.sync m16n8k8 tf32: D += A*B, row.col, fp32 accum
__device__ __forceinline__ void mma_tf32(float* d, const uint32_t* a, const uint32_t* b) {
    asm volatile(
        "mma.sync.aligned.m16n8k8.row.col.f32.tf32.tf32.f32 "
        "{%0,%1,%2,%3}, {%4,%5,%6,%7}, {%8,%9}, {%0,%1,%2,%3};"
        : "+f"(d[0]), "+f"(d[1]), "+f"(d[2]), "+f"(d[3])
        : "r"(a[0]), "r"(a[1]), "r"(a[2]), "r"(a[3]),
          "r"(b[0]), "r"(b[1]));
}

__device__ __forceinline__ void ldsm_x4(uint32_t* r, uint32_t addr) {
    asm volatile("ldmatrix.sync.aligned.m8n8.x4.shared.b16 {%0,%1,%2,%3}, [%4];"
                 : "=r"(r[0]), "=r"(r[1]), "=r"(r[2]), "=r"(r[3]) : "r"(addr));
}

__device__ __forceinline__ void ldsm_x2(uint32_t* r, uint32_t addr) {
    asm volatile("ldmatrix.sync.aligned.m8n8.x2.shared.b16 {%0,%1}, [%2];"
                 : "=r"(r[0]), "=r"(r[1]) : "r"(addr));
}

// ---------------------------------------------------------------------------
// Robust length read (int64 vs int32 l buffer)
// ---------------------------------------------------------------------------
__device__ __forceinline__ int get_len(const int* __restrict__ p, int b) {
    bool is64 = ((p[1] | p[3] | p[5] | p[7]) == 0);
    return is64 ? p[2 * b] : p[b];
}

// ---------------------------------------------------------------------------
// Pre-pass: round fp32 -> nearest tf32-representable fp32 (vectorized)
// ---------------------------------------------------------------------------
__global__ void round_tf32_kernel(const float4* __restrict__ in,
                                  float4* __restrict__ out, int n4) {
    int i = blockIdx.x * blockDim.x + threadIdx.x;
    if (i < n4) {
        float4 v = in[i];
        float4 o;
        o.x = __uint_as_float(f2tf32(v.x));
        o.y = __uint_as_float(f2tf32(v.y));
        o.z = __uint_as_float(f2tf32(v.z));
        o.w = __uint_as_float(f2tf32(v.w));
        out[i] = o;
    }
}

// ---------------------------------------------------------------------------
// Kernel A: QKV projection GEMM (mma.sync tf32 + ldmatrix, pre-rounded inputs)
// C[m,n] = round_tf32( sum_k A[m,k]*W[n,k] + bias[n] )
// CTA 256x128, BK=32, 3-stage cp.async, 512 threads (16 warps 4x4), warp 64x32
// ---------------------------------------------------------------------------
#define BM 256
#define BN 128
#define BK 32
#define NK (1024 / BK)    // 32
#define NSTG 3
#define ROWP 36
#define STG_FLOATS ((BM + BN) * ROWP)                 // 13824 floats
#define SMEM_GEMM_TOTAL (NSTG * STG_FLOATS * 4)       // 165888 bytes

__global__ __launch_bounds__(512) void qkv_gemm_mma(
    const float* __restrict__ A,
    const float* __restrict__ W,
    const float* __restrict__ bias,
    float* __restrict__ C)
{
    extern __shared__ float sm[];

    const int tid  = threadIdx.x;
    const int wid  = tid >> 5;
    const int lane = tid & 31;
    const int g = lane >> 2;
    const int c = lane & 3;
    const int wm = wid >> 2;      // 0..3 (64 rows each)
    const int wn = wid & 3;       // 0..3 (32 cols each)
    const int bm = blockIdx.y * BM;
    const int bn = blockIdx.x * BN;

    float acc[4][4][4];
#pragma unroll
    for (int mi = 0; mi < 4; mi++)
#pragma unroll
        for (int ni = 0; ni < 4; ni++)
#pragma unroll
            for (int r = 0; r < 4; r++) acc[mi][ni][r] = 0.f;

    const uint32_t sm_u = smem_u32(sm);

    // ldmatrix per-lane base offsets (bytes within a stage)
    // A fragment (x4): rows = warp m-block row + (lane&15), col = (lane>>4)*4
    const uint32_t a_base = ((uint32_t)((wm * 64 + (lane & 15)) * ROWP
                                        + ((lane >> 4) << 2))) * 4;
    // B fragment (x2): rows = warp n-block row + (lane&7), col = ((lane>>3)&1)*4
    const uint32_t b_base = ((uint32_t)((BM + wn * 32 + (lane & 7)) * ROWP
                                        + (((lane >> 3) & 1) << 2))) * 4;

    // ---- stage loader: A 256x32 + B 128x32 floats = 3072 float4, 512 thr ----
#define LOAD_STAGE(kt, s)                                                      \
    {                                                                          \
        const int kof = (kt) * BK;                                             \
        const uint32_t dst = sm_u + (uint32_t)(s) * (STG_FLOATS * 4);          \
        _Pragma("unroll")                                                      \
        for (int f = 0; f < 6; f++) {                                          \
            const int idx = f * 512 + tid;                                     \
            if (idx < 2048) {                                                  \
                const int row = idx >> 3;                                      \
                const int c4  = (idx & 7) << 2;                                \
                cp16(dst + (row * ROWP + c4) * 4,                              \
                     A + (size_t)(bm + row) * 1024 + kof + c4);                \
            } else {                                                           \
                const int gdx = idx - 2048;                                    \
                const int row = gdx >> 3;                                      \
                const int c4  = (gdx & 7) << 2;                                \
                cp16(dst + ((BM + row) * ROWP + c4) * 4,                       \
                     W + (size_t)(bn + row) * 1024 + kof + c4);                \
            }                                                                  \
        }                                                                      \
        asm volatile("cp.async.commit_group;" ::: "memory");                   \
    }

    LOAD_STAGE(0, 0);
    LOAD_STAGE(1, 1);

#pragma unroll 1
    for (int kt = 0; kt < NK; kt++) {
        asm volatile("cp.async.wait_group 1;" ::: "memory");
        __syncthreads();

        if (kt + 2 < NK) {
            const int s2 = (kt + 2) % NSTG;
            LOAD_STAGE(kt + 2, s2);
        }

        const uint32_t stg = sm_u + (uint32_t)(kt % NSTG) * (STG_FLOATS * 4);
        const uint32_t aB = stg + a_base;
        const uint32_t bB = stg + b_base;

#pragma unroll
        for (int kk = 0; kk < 4; kk++) {
            uint32_t af[4][4], bf[4][2];
#pragma unroll
            for (int mi = 0; mi < 4; mi++)
                ldsm_x4(af[mi], aB + (uint32_t)((mi * 16 * ROWP + kk * 8) * 4));
#pragma unroll
            for (int ni = 0; ni < 4; ni++)
                ldsm_x2(bf[ni], bB + (uint32_t)((ni * 8 * ROWP + kk * 8) * 4));
#pragma unroll
            for (int mi = 0; mi < 4; mi++)
#pragma unroll
                for (int ni = 0; ni < 4; ni++)
                    mma_tf32(acc[mi][ni], af[mi], bf[ni]);
        }
    }

    // ---- epilogue: bias, round to tf32-representable, store ----
#pragma unroll
    for (int mi = 0; mi < 4; mi++) {
        const int r0 = bm + wm * 64 + mi * 16 + g;
#pragma unroll
        for (int ni = 0; ni < 4; ni++) {
            const int col = bn + wn * 32 + ni * 8 + c * 2;
            const float bx = __ldg(bias + col);
            const float by = __ldg(bias + col + 1);
            float2 v0, v1;
            v0.x = __uint_as_float(f2tf32(acc[mi][ni][0] + bx));
            v0.y = __uint_as_float(f2tf32(acc[mi][ni][1] + by));
            v1.x = __uint_as_float(f2tf32(acc[mi][ni][2] + bx));
            v1.y = __uint_as_float(f2tf32(acc[mi][ni][3] + by));
            *(float2*)(C + (size_t)r0 * E3 + col) = v0;
            *(float2*)(C + (size_t)(r0 + 8) * E3 + col) = v1;
        }
    }
}

// ---------------------------------------------------------------------------
// Kernel B: flash attention on tensor cores (mma.sync tf32)
// qkv values are already tf32-representable -> no cvt needed for Q/K/V frags.
// P (exp outputs) still rounded with cvt.rna to avoid truncation bias.
// ---------------------------------------------------------------------------
#define ATT_T   4352                 // 64*68 floats per tile buffer
#define ATT_SMEM ((size_t)(5 * ATT_T) * 4)   // 87040 bytes

__global__ __launch_bounds__(128) void attn_mma(
    const float* __restrict__ qkv,
    const int* __restrict__ lens,
    float* __restrict__ out)
{
    extern __shared__ float smf[];
    float* QP = smf + 4 * ATT_T;

    const int tid  = threadIdx.x;
    const int wid  = tid >> 5;
    const int lane = tid & 31;
    const int g = lane >> 2;
    const int c = lane & 3;

    const int qt = blockIdx.x;
    const int h  = blockIdx.y;
    const int b  = blockIdx.z;
    const int L  = get_len(lens, b);
    const int qbase = qt * 64;

    float* outp = out + ((size_t)(b * SEQ + qbase)) * EMB + h * DHEAD;

    if (qbase >= L) {
        float4 z = make_float4(0.f, 0.f, 0.f, 0.f);
#pragma unroll
        for (int t = 0; t < 8; t++) {
            int idx = t * 128 + tid;
            int row = idx >> 4, c4 = (idx & 15) << 2;
            *(float4*)(outp + (size_t)row * EMB + c4) = z;
        }
        return;
    }

    {
        const float* qgp = qkv + ((size_t)(b * SEQ + qbase)) * E3 + h * DHEAD;
#pragma unroll
        for (int t = 0; t < 8; t++) {
            int idx = t * 128 + tid;
            int row = idx >> 4, c4 = (idx & 15) << 2;
            *(float4*)&QP[row * 68 + c4] = *(const float4*)(qgp + (size_t)row * E3 + c4);
        }
    }
    __syncthreads();

    uint32_t qf[8][4];
    {
        const int r0 = wid * 16 + g;
#pragma unroll
        for (int kk = 0; kk < 8; kk++) {
            // scale by 2^-5 is exact; values stay tf32-representable
            qf[kk][0] = __float_as_uint(QP[r0 * 68 + kk * 8 + c] * 0.03125f);
            qf[kk][1] = __float_as_uint(QP[(r0 + 8) * 68 + kk * 8 + c] * 0.03125f);
            qf[kk][2] = __float_as_uint(QP[r0 * 68 + kk * 8 + c + 4] * 0.03125f);
            qf[kk][3] = __float_as_uint(QP[(r0 + 8) * 68 + kk * 8 + c + 4] * 0.03125f);
        }
    }

    const uint32_t sm_u = smem_u32(smf);
    const int ktmax = min(qt, (L - 1) >> 6);

#define KV_LOAD(kt, buf)                                                        \
    {                                                                           \
        const float* kgp = qkv + ((size_t)(b * SEQ + (kt) * 64)) * E3           \
                           + EMB + h * DHEAD;                                   \
        const uint32_t dK = sm_u + (uint32_t)((buf) * ATT_T) * 4;               \
        const uint32_t dV = sm_u + (uint32_t)((2 + (buf)) * ATT_T) * 4;         \
        _Pragma("unroll")                                                       \
        for (int t = 0; t < 8; t++) {                                           \
            int idx = t * 128 + tid;                                            \
            int row = idx >> 4, c4 = (idx & 15) << 2;                           \
            cp16(dK + (row * 68 + c4) * 4, kgp + (size_t)row * E3 + c4);        \
            cp16(dV + (row * 68 + c4) * 4, kgp + (size_t)row * E3 + EMB + c4);  \
        }                                                                       \
        asm volatile("cp.async.commit_group;" ::: "memory");                    \
    }

    KV_LOAD(0, 0);

    float m0 = -1e30f, m1 = -1e30f, l0 = 0.f, l1 = 0.f;
    float oacc[8][4];
#pragma unroll
    for (int dt = 0; dt < 8; dt++)
#pragma unroll
        for (int r = 0; r < 4; r++) oacc[dt][r] = 0.f;

    float* Pw = QP + (wid * 16) * 68;

#pragma unroll 1
    for (int kt = 0; kt <= ktmax; kt++) {
        if (kt < ktmax) KV_LOAD(kt + 1, (kt + 1) & 1);
        if (kt < ktmax) asm volatile("cp.async.wait_group 1;" ::: "memory");
        else            asm volatile("cp.async.wait_group 0;" ::: "memory");
        __syncthreads();

        const float* Kp = smf + (kt & 1) * ATT_T;
        const float* Vp = smf + (2 + (kt & 1)) * ATT_T;

        float sacc[8][4];
#pragma unroll
        for (int nt = 0; nt < 8; nt++)
#pragma unroll
            for (int r = 0; r < 4; r++) sacc[nt][r] = 0.f;

#pragma unroll
        for (int kk = 0; kk < 8; kk++) {
#pragma unroll
            for (int nt = 0; nt < 8; nt++) {
                uint32_t bf[2];
                bf[0] = __float_as_uint(Kp[(nt * 8 + g) * 68 + kk * 8 + c]);
                bf[1] = __float_as_uint(Kp[(nt * 8 + g) * 68 + kk * 8 + c + 4]);
                mma_tf32(sacc[nt], qf[kk], bf);
            }
        }

        if (kt == qt) {
            const int lr0 = wid * 16 + g;
            const int lr1 = lr0 + 8;
#pragma unroll
            for (int nt = 0; nt < 8; nt++) {
                const int col0 = nt * 8 + 2 * c;
                if (col0 > lr0)     sacc[nt][0] = -1e30f;
                if (col0 + 1 > lr0) sacc[nt][1] = -1e30f;
                if (col0 > lr1)     sacc[nt][2] = -1e30f;
                if (col0 + 1 > lr1) sacc[nt][3] = -1e30f;
            }
        }

        float tm0 = -1e30f, tm1 = -1e30f;
#pragma unroll
        for (int nt = 0; nt < 8; nt++) {
            tm0 = fmaxf(tm0, fmaxf(sacc[nt][0], sacc[nt][1]));
            tm1 = fmaxf(tm1, fmaxf(sacc[nt][2], sacc[nt][3]));
        }
        tm0 = fmaxf(tm0, __shfl_xor_sync(0xFFFFFFFF, tm0, 1));
        tm0 = fmaxf(tm0, __shfl_xor_sync(0xFFFFFFFF, tm0, 2));
        tm1 = fmaxf(tm1, __shfl_xor_sync(0xFFFFFFFF, tm1, 1));
        tm1 = fmaxf(tm1, __shfl_xor_sync(0xFFFFFFFF, tm1, 2));

        const float nm0 = fmaxf(m0, tm0);
        const float nm1 = fmaxf(m1, tm1);
        const float cor0 = __expf(m0 - nm0);
        const float cor1 = __expf(m1 - nm1);
        l0 *= cor0; l1 *= cor1;
#pragma unroll
        for (int dt = 0; dt < 8; dt++) {
            oacc[dt][0] *= cor0; oacc[dt][1] *= cor0;
            oacc[dt][2] *= cor1; oacc[dt][3] *= cor1;
        }

        float ps0 = 0.f, ps1 = 0.f;
#pragma unroll
        for (int nt = 0; nt < 8; nt++) {
            const float p0 = __expf(sacc[nt][0] - nm0);
            const float p1 = __expf(sacc[nt][1] - nm0);
            const float p2 = __expf(sacc[nt][2] - nm1);
            const float p3 = __expf(sacc[nt][3] - nm1);
            ps0 += p0 + p1; ps1 += p2 + p3;
            Pw[g * 68 + nt * 8 + 2 * c]           = p0;
            Pw[g * 68 + nt * 8 + 2 * c + 1]       = p1;
            Pw[(g + 8) * 68 + nt * 8 + 2 * c]     = p2;
            Pw[(g + 8) * 68 + nt * 8 + 2 * c + 1] = p3;
        }
        ps0 += __shfl_xor_sync(0xFFFFFFFF, ps0, 1);
        ps0 += __shfl_xor_sync(0xFFFFFFFF, ps0, 2);
        ps1 += __shfl_xor_sync(0xFFFFFFFF, ps1, 1);
        ps1 += __shfl_xor_sync(0xFFFFFFFF, ps1, 2);
        l0 += ps0; l1 += ps1;
        m0 = nm0; m1 = nm1;
        __syncwarp();

#pragma unroll
        for (int kvc = 0; kvc < 8; kvc++) {
            uint32_t pf[4];
            pf[0] = f2tf32(Pw[g * 68 + kvc * 8 + c]);
            pf[1] = f2tf32(Pw[(g + 8) * 68 + kvc * 8 + c]);
            pf[2] = f2tf32(Pw[g * 68 + kvc * 8 + c + 4]);
            pf[3] = f2tf32(Pw[(g + 8) * 68 + kvc * 8 + c + 4]);
#pragma unroll
            for (int dt = 0; dt < 8; dt++) {
                uint32_t bf[2];
                bf[0] = __float_as_uint(Vp[(kvc * 8 + c) * 68 + dt * 8 + g]);
                bf[1] = __float_as_uint(Vp[(kvc * 8 + c + 4) * 68 + dt * 8 + g]);
                mma_tf32(oacc[dt], pf, bf);
            }
        }
        __syncthreads();
    }

    const float inv0 = 1.0f / l0;
    const float inv1 = 1.0f / l1;
    const int q0row = qbase + wid * 16 + g;
    const int q1row = q0row + 8;
    const bool v0 = (q0row < L);
    const bool v1 = (q1row < L);
    float* o0 = out + ((size_t)(b * SEQ + q0row)) * EMB + h * DHEAD;
    float* o1 = out + ((size_t)(b * SEQ + q1row)) * EMB + h * DHEAD;
#pragma unroll
    for (int dt = 0; dt < 8; dt++) {
        const int col = dt * 8 + 2 * c;
        float2 r0 = v0 ? make_float2(oacc[dt][0] * inv0, oacc[dt][1] * inv0)
                       : make_float2(0.f, 0.f);
        float2 r1 = v1 ? make_float2(oacc[dt][2] * inv1, oacc[dt][3] * inv1)
                       : make_float2(0.f, 0.f);
        *(float2*)(o0 + col) = r0;
        *(float2*)(o1 + col) = r1;
    }
}

// ---------------------------------------------------------------------------
// Launch
// ---------------------------------------------------------------------------
extern "C" void kernel_launch(void* const* d_in, const int* in_sizes, int n_in,
                              void* d_out, int out_size) {
    const float* x = nullptr;
    const int*   l = nullptr;
    const float* W = nullptr;
    const float* bias = nullptr;
    for (int i = 0; i < n_in; i++) {
        switch (in_sizes[i]) {
            case 8388608: x    = (const float*)d_in[i]; break;
            case 8:       l    = (const int*)d_in[i];   break;
            case 3145728: W    = (const float*)d_in[i]; break;
            case 3072:    bias = (const float*)d_in[i]; break;
            default: break;
        }
    }
    float* out = (float*)d_out;

    float *qkv_ptr = nullptr, *xr_ptr = nullptr, *wr_ptr = nullptr;
    cudaGetSymbolAddress((void**)&qkv_ptr, g_qkv);
    cudaGetSymbolAddress((void**)&xr_ptr,  g_xr);
    cudaGetSymbolAddress((void**)&wr_ptr,  g_wr);

    static bool attr_set = false;
    if (!attr_set) {
        cudaFuncSetAttribute(qkv_gemm_mma,
                             cudaFuncAttributeMaxDynamicSharedMemorySize,
                             SMEM_GEMM_TOTAL);
        cudaFuncSetAttribute(attn_mma,
                             cudaFuncAttributeMaxDynamicSharedMemorySize,
                             (int)ATT_SMEM);
        attr_set = true;
    }

    // Pre-round x and W to tf32-representable fp32
    {
        const int n4x = (BATCH * SEQ * EMB) / 4;   // 2097152
        const int n4w = (E3 * EMB) / 4;            // 786432
        round_tf32_kernel<<<n4x / 256, 256>>>((const float4*)x, (float4*)xr_ptr, n4x);
        round_tf32_kernel<<<n4w / 256, 256>>>((const float4*)W, (float4*)wr_ptr, n4w);
    }

    dim3 gg(E3 / BN, (BATCH * SEQ) / BM);     // (24, 32)
    qkv_gemm_mma<<<gg, 512, SMEM_GEMM_TOTAL>>>(xr_ptr, wr_ptr, bias, qkv_ptr);

    dim3 ga(SEQ / 64, NHEAD, BATCH);          // (16, 16, 8)
    attn_mma<<<ga, 128, ATT_SMEM>>>(qkv_ptr, l, out);
}

// round 7
// speedup vs baseline: 5.6257x; 1.6229x over previous
#include <cuda_runtime.h>
#include <cuda_fp16.h>
#include <cstdint>
#include <cstddef>

// Problem constants
#define BATCH 8
#define SEQ   1024
#define EMB   1024
#define NHEAD 16
#define DHEAD 64
#define E3    3072   // 3*EMB

// Scratch: fp16 copies of x and W, fp16 QKV projection output
__device__ __half g_xh[(size_t)BATCH * SEQ * EMB];
__device__ __half g_wh[(size_t)E3 * EMB];
__device__ __half g_qkvh[(size_t)BATCH * SEQ * E3];

// ---------------------------------------------------------------------------
// Helpers
// ---------------------------------------------------------------------------
__device__ __forceinline__ uint32_t h2_bits(__half2 h) {
    return *reinterpret_cast<uint32_t*>(&h);
}

__device__ __forceinline__ uint32_t smem_u32(const void* p) {
    uint32_t a;
    asm("{ .reg .u64 t; cvta.to.shared.u64 t, %1; cvt.u32.u64 %0, t; }"
        : "=r"(a) : "l"(p));
    return a;
}

__device__ __forceinline__ void cp16(uint32_t dst, const void* src) {
    asm volatile("cp.async.cg.shared.global [%0], [%1], 16;"
                 :: "r"(dst), "l"(src) : "memory");
}

// mma.sync m16n8k16 f16 with fp32 accum: D += A*B, row.col
__device__ __forceinline__ void mma_f16(float* d, const uint32_t* a, const uint32_t* b) {
    asm volatile(
        "mma.sync.aligned.m16n8k16.row.col.f32.f16.f16.f32 "
        "{%0,%1,%2,%3}, {%4,%5,%6,%7}, {%8,%9}, {%0,%1,%2,%3};"
        : "+f"(d[0]), "+f"(d[1]), "+f"(d[2]), "+f"(d[3])
        : "r"(a[0]), "r"(a[1]), "r"(a[2]), "r"(a[3]),
          "r"(b[0]), "r"(b[1]));
}

__device__ __forceinline__ void ldsm_x4(uint32_t* r, uint32_t addr) {
    asm volatile("ldmatrix.sync.aligned.m8n8.x4.shared.b16 {%0,%1,%2,%3}, [%4];"
                 : "=r"(r[0]), "=r"(r[1]), "=r"(r[2]), "=r"(r[3]) : "r"(addr));
}

__device__ __forceinline__ void ldsm_x2(uint32_t* r, uint32_t addr) {
    asm volatile("ldmatrix.sync.aligned.m8n8.x2.shared.b16 {%0,%1}, [%2];"
                 : "=r"(r[0]), "=r"(r[1]) : "r"(addr));
}

// ---------------------------------------------------------------------------
// Robust length read (int64 vs int32 l buffer)
// ---------------------------------------------------------------------------
__device__ __forceinline__ int get_len(const int* __restrict__ p, int b) {
    bool is64 = ((p[1] | p[3] | p[5] | p[7]) == 0);
    return is64 ? p[2 * b] : p[b];
}

// ---------------------------------------------------------------------------
// Pre-pass: fp32 -> fp16
// ---------------------------------------------------------------------------
__global__ void to_half_kernel(const float4* __restrict__ in,
                               uint2* __restrict__ out, int n4) {
    int i = blockIdx.x * blockDim.x + threadIdx.x;
    if (i < n4) {
        float4 v = in[i];
        uint2 o;
        o.x = h2_bits(__floats2half2_rn(v.x, v.y));
        o.y = h2_bits(__floats2half2_rn(v.z, v.w));
        out[i] = o;
    }
}

// ---------------------------------------------------------------------------
// Kernel A: QKV projection GEMM (mma.sync f16, fp32 accum)
// C[m,n] = half( sum_k A[m,k]*W[n,k] + bias[n] )
// CTA 256x128, BK=32 halves, 3-stage cp.async, 512 threads, warp 64x32.
// smem tile rows padded to 40 halves (80B) -> ldmatrix conflict-free.
// ---------------------------------------------------------------------------
#define BM 256
#define BN 128
#define BKH 32
#define NKI (1024 / BKH)    // 32
#define NSTG 3
#define RPH 40
#define STG_HALVES ((BM + BN) * RPH)                  // 15360
#define SMEM_GEMM_TOTAL (NSTG * STG_HALVES * 2)       // 92160 bytes

__global__ __launch_bounds__(512) void qkv_gemm_h(
    const __half* __restrict__ A,
    const __half* __restrict__ W,
    const float* __restrict__ bias,
    __half* __restrict__ C)
{
    extern __shared__ __half smh[];

    const int tid  = threadIdx.x;
    const int wid  = tid >> 5;
    const int lane = tid & 31;
    const int g = lane >> 2;
    const int c = lane & 3;
    const int wm = wid >> 2;      // 0..3 (64 rows)
    const int wn = wid & 3;       // 0..3 (32 cols)
    const int bm = blockIdx.y * BM;
    const int bn = blockIdx.x * BN;

    float acc[4][4][4];
#pragma unroll
    for (int mi = 0; mi < 4; mi++)
#pragma unroll
        for (int ni = 0; ni < 4; ni++)
#pragma unroll
            for (int r = 0; r < 4; r++) acc[mi][ni][r] = 0.f;

    const uint32_t sm_u = smem_u32(smh);

    // ldmatrix lane base offsets (bytes within stage)
    const uint32_t a_base = ((uint32_t)((wm * 64 + (lane & 15)) * RPH
                                        + ((lane >> 4) << 3))) * 2;
    const uint32_t b_base = ((uint32_t)((BM + wn * 32 + (lane & 7)) * RPH
                                        + (((lane >> 3) & 1) << 3))) * 2;

    // stage loader: A 256 rows x 4 chunks + B 128 x 4 chunks (16B each) = 1536
#define LOAD_STAGE(kt, s)                                                      \
    {                                                                          \
        const int kof = (kt) * BKH;                                            \
        const uint32_t dst = sm_u + (uint32_t)(s) * (STG_HALVES * 2);          \
        _Pragma("unroll")                                                      \
        for (int f = 0; f < 3; f++) {                                          \
            const int idx = f * 512 + tid;                                     \
            if (idx < 1024) {                                                  \
                const int row = idx >> 2;                                      \
                const int ch  = (idx & 3) << 3;                                \
                cp16(dst + (row * RPH + ch) * 2,                               \
                     A + (size_t)(bm + row) * 1024 + kof + ch);                \
            } else {                                                           \
                const int gdx = idx - 1024;                                    \
                const int row = gdx >> 2;                                      \
                const int ch  = (gdx & 3) << 3;                                \
                cp16(dst + ((BM + row) * RPH + ch) * 2,                        \
                     W + (size_t)(bn + row) * 1024 + kof + ch);                \
            }                                                                  \
        }                                                                      \
        asm volatile("cp.async.commit_group;" ::: "memory");                   \
    }

    LOAD_STAGE(0, 0);
    LOAD_STAGE(1, 1);

#pragma unroll 1
    for (int kt = 0; kt < NKI; kt++) {
        asm volatile("cp.async.wait_group 1;" ::: "memory");
        __syncthreads();

        if (kt + 2 < NKI) {
            const int s2 = (kt + 2) % NSTG;
            LOAD_STAGE(kt + 2, s2);
        }

        const uint32_t stg = sm_u + (uint32_t)(kt % NSTG) * (STG_HALVES * 2);
        const uint32_t aB = stg + a_base;
        const uint32_t bB = stg + b_base;

#pragma unroll
        for (int kk = 0; kk < 2; kk++) {      // 2 x K=16 per BK=32
            uint32_t af[4][4], bf[4][2];
#pragma unroll
            for (int mi = 0; mi < 4; mi++)
                ldsm_x4(af[mi], aB + (uint32_t)((mi * 16 * RPH + kk * 16) * 2));
#pragma unroll
            for (int ni = 0; ni < 4; ni++)
                ldsm_x2(bf[ni], bB + (uint32_t)((ni * 8 * RPH + kk * 16) * 2));
#pragma unroll
            for (int mi = 0; mi < 4; mi++)
#pragma unroll
                for (int ni = 0; ni < 4; ni++)
                    mma_f16(acc[mi][ni], af[mi], bf[ni]);
        }
    }

    // epilogue: bias, convert to half, store
#pragma unroll
    for (int mi = 0; mi < 4; mi++) {
        const int r0 = bm + wm * 64 + mi * 16 + g;
#pragma unroll
        for (int ni = 0; ni < 4; ni++) {
            const int col = bn + wn * 32 + ni * 8 + c * 2;
            const float bx = __ldg(bias + col);
            const float by = __ldg(bias + col + 1);
            __half2 v0 = __floats2half2_rn(acc[mi][ni][0] + bx, acc[mi][ni][1] + by);
            __half2 v1 = __floats2half2_rn(acc[mi][ni][2] + bx, acc[mi][ni][3] + by);
            *(__half2*)(C + (size_t)r0 * E3 + col) = v0;
            *(__half2*)(C + (size_t)(r0 + 8) * E3 + col) = v1;
        }
    }
}

// ---------------------------------------------------------------------------
// Kernel B: flash attention, fp16 operands, fp32 accum/softmax.
// Block: 128 threads (4 warps) per (b, h, 64-row q tile). Bc = 64.
// smem halves: K[2][64*72], V[2][64*72], QP[64*72]  (rows padded to 72)
// ---------------------------------------------------------------------------
#define ATT_TH 4608                       // 64*72 halves
#define ATT_SMEM (5 * ATT_TH * 2)         // 46080 bytes

__global__ __launch_bounds__(128) void attn_h(
    const __half* __restrict__ qkv,
    const int* __restrict__ lens,
    float* __restrict__ out)
{
    extern __shared__ __half smh[];
    __half* QP = smh + 4 * ATT_TH;

    const int tid  = threadIdx.x;
    const int wid  = tid >> 5;
    const int lane = tid & 31;
    const int g = lane >> 2;
    const int c = lane & 3;

    const int qt = blockIdx.x;
    const int h  = blockIdx.y;
    const int b  = blockIdx.z;
    const int L  = get_len(lens, b);
    const int qbase = qt * 64;

    float* outp = out + ((size_t)(b * SEQ + qbase)) * EMB + h * DHEAD;

    if (qbase >= L) {
        float4 z = make_float4(0.f, 0.f, 0.f, 0.f);
#pragma unroll
        for (int t = 0; t < 8; t++) {
            int idx = t * 128 + tid;
            int row = idx >> 4, c4 = (idx & 15) << 2;
            *(float4*)(outp + (size_t)row * EMB + c4) = z;
        }
        return;
    }

    // load Q tile (64 rows x 64 halves) into QP
    {
        const __half* qgp = qkv + ((size_t)(b * SEQ + qbase)) * E3 + h * DHEAD;
#pragma unroll
        for (int t = 0; t < 4; t++) {
            int idx = t * 128 + tid;
            int row = idx >> 3, ch = (idx & 7) << 3;
            *(uint4*)&QP[row * 72 + ch] = *(const uint4*)(qgp + (size_t)row * E3 + ch);
        }
    }
    __syncthreads();

    // Q fragments, pre-scaled by 1/32 (exact in fp16)
    uint32_t qf[4][4];
    {
        const __half2 qs = __float2half2_rn(0.03125f);
        const int r0 = wid * 16 + g;
#pragma unroll
        for (int kk = 0; kk < 4; kk++) {
            __half2 t0 = __hmul2(*(__half2*)&QP[r0 * 72 + kk * 16 + 2 * c], qs);
            __half2 t1 = __hmul2(*(__half2*)&QP[(r0 + 8) * 72 + kk * 16 + 2 * c], qs);
            __half2 t2 = __hmul2(*(__half2*)&QP[r0 * 72 + kk * 16 + 2 * c + 8], qs);
            __half2 t3 = __hmul2(*(__half2*)&QP[(r0 + 8) * 72 + kk * 16 + 2 * c + 8], qs);
            qf[kk][0] = h2_bits(t0);
            qf[kk][1] = h2_bits(t1);
            qf[kk][2] = h2_bits(t2);
            qf[kk][3] = h2_bits(t3);
        }
    }

    const uint32_t sm_u = smem_u32(smh);
    const int ktmax = min(qt, (L - 1) >> 6);

    // KV tile loader: 64 rows x 8 chunks of 16B for each of K, V
#define KV_LOAD(kt, buf)                                                        \
    {                                                                           \
        const __half* kgp = qkv + ((size_t)(b * SEQ + (kt) * 64)) * E3          \
                            + EMB + h * DHEAD;                                  \
        const uint32_t dK = sm_u + (uint32_t)((buf) * ATT_TH) * 2;              \
        const uint32_t dV = sm_u + (uint32_t)((2 + (buf)) * ATT_TH) * 2;        \
        _Pragma("unroll")                                                       \
        for (int t = 0; t < 8; t++) {                                           \
            int idx = t * 128 + tid;                                            \
            if (idx < 512) {                                                    \
                int row = idx >> 3, ch = (idx & 7) << 3;                        \
                cp16(dK + (row * 72 + ch) * 2, kgp + (size_t)row * E3 + ch);    \
            } else {                                                            \
                int jdx = idx - 512;                                            \
                int row = jdx >> 3, ch = (jdx & 7) << 3;                        \
                cp16(dV + (row * 72 + ch) * 2,                                  \
                     kgp + (size_t)row * E3 + EMB + ch);                        \
            }                                                                   \
        }                                                                       \
        asm volatile("cp.async.commit_group;" ::: "memory");                    \
    }

    KV_LOAD(0, 0);

    float m0 = -1e30f, m1 = -1e30f, l0 = 0.f, l1 = 0.f;
    float oacc[8][4];
#pragma unroll
    for (int dt = 0; dt < 8; dt++)
#pragma unroll
        for (int r = 0; r < 4; r++) oacc[dt][r] = 0.f;

    __half* Pw = QP + (wid * 16) * 72;

#pragma unroll 1
    for (int kt = 0; kt <= ktmax; kt++) {
        if (kt < ktmax) KV_LOAD(kt + 1, (kt + 1) & 1);
        if (kt < ktmax) asm volatile("cp.async.wait_group 1;" ::: "memory");
        else            asm volatile("cp.async.wait_group 0;" ::: "memory");
        __syncthreads();

        const __half* Kp = smh + (kt & 1) * ATT_TH;
        const __half* Vp = smh + (2 + (kt & 1)) * ATT_TH;

        // ---- S = Q @ K^T ----
        float sacc[8][4];
#pragma unroll
        for (int nt = 0; nt < 8; nt++)
#pragma unroll
            for (int r = 0; r < 4; r++) sacc[nt][r] = 0.f;

#pragma unroll
        for (int kk = 0; kk < 4; kk++) {
#pragma unroll
            for (int nt = 0; nt < 8; nt++) {
                uint32_t bf[2];
                bf[0] = *(const uint32_t*)&Kp[(nt * 8 + g) * 72 + kk * 16 + 2 * c];
                bf[1] = *(const uint32_t*)&Kp[(nt * 8 + g) * 72 + kk * 16 + 2 * c + 8];
                mma_f16(sacc[nt], qf[kk], bf);
            }
        }

        // ---- causal mask (diagonal tile only) ----
        if (kt == qt) {
            const int lr0 = wid * 16 + g;
            const int lr1 = lr0 + 8;
#pragma unroll
            for (int nt = 0; nt < 8; nt++) {
                const int col0 = nt * 8 + 2 * c;
                if (col0 > lr0)     sacc[nt][0] = -1e30f;
                if (col0 + 1 > lr0) sacc[nt][1] = -1e30f;
                if (col0 > lr1)     sacc[nt][2] = -1e30f;
                if (col0 + 1 > lr1) sacc[nt][3] = -1e30f;
            }
        }

        // ---- online softmax ----
        float tm0 = -1e30f, tm1 = -1e30f;
#pragma unroll
        for (int nt = 0; nt < 8; nt++) {
            tm0 = fmaxf(tm0, fmaxf(sacc[nt][0], sacc[nt][1]));
            tm1 = fmaxf(tm1, fmaxf(sacc[nt][2], sacc[nt][3]));
        }
        tm0 = fmaxf(tm0, __shfl_xor_sync(0xFFFFFFFF, tm0, 1));
        tm0 = fmaxf(tm0, __shfl_xor_sync(0xFFFFFFFF, tm0, 2));
        tm1 = fmaxf(tm1, __shfl_xor_sync(0xFFFFFFFF, tm1, 1));
        tm1 = fmaxf(tm1, __shfl_xor_sync(0xFFFFFFFF, tm1, 2));

        const float nm0 = fmaxf(m0, tm0);
        const float nm1 = fmaxf(m1, tm1);
        const float cor0 = __expf(m0 - nm0);
        const float cor1 = __expf(m1 - nm1);
        l0 *= cor0; l1 *= cor1;
#pragma unroll
        for (int dt = 0; dt < 8; dt++) {
            oacc[dt][0] *= cor0; oacc[dt][1] *= cor0;
            oacc[dt][2] *= cor1; oacc[dt][3] *= cor1;
        }

        float ps0 = 0.f, ps1 = 0.f;
#pragma unroll
        for (int nt = 0; nt < 8; nt++) {
            const float p0 = __expf(sacc[nt][0] - nm0);
            const float p1 = __expf(sacc[nt][1] - nm0);
            const float p2 = __expf(sacc[nt][2] - nm1);
            const float p3 = __expf(sacc[nt][3] - nm1);
            ps0 += p0 + p1; ps1 += p2 + p3;
            *(__half2*)&Pw[g * 72 + nt * 8 + 2 * c]       = __floats2half2_rn(p0, p1);
            *(__half2*)&Pw[(g + 8) * 72 + nt * 8 + 2 * c] = __floats2half2_rn(p2, p3);
        }
        ps0 += __shfl_xor_sync(0xFFFFFFFF, ps0, 1);
        ps0 += __shfl_xor_sync(0xFFFFFFFF, ps0, 2);
        ps1 += __shfl_xor_sync(0xFFFFFFFF, ps1, 1);
        ps1 += __shfl_xor_sync(0xFFFFFFFF, ps1, 2);
        l0 += ps0; l1 += ps1;
        m0 = nm0; m1 = nm1;
        __syncwarp();

        // ---- O += P @ V ----
#pragma unroll
        for (int kk = 0; kk < 4; kk++) {
            uint32_t pf[4];
            pf[0] = *(const uint32_t*)&Pw[g * 72 + kk * 16 + 2 * c];
            pf[1] = *(const uint32_t*)&Pw[(g + 8) * 72 + kk * 16 + 2 * c];
            pf[2] = *(const uint32_t*)&Pw[g * 72 + kk * 16 + 2 * c + 8];
            pf[3] = *(const uint32_t*)&Pw[(g + 8) * 72 + kk * 16 + 2 * c + 8];
            const int kv0 = kk * 16 + 2 * c;
#pragma unroll
            for (int dt = 0; dt < 8; dt++) {
                const int col = dt * 8 + g;
                __half2 b0 = __halves2half2(Vp[kv0 * 72 + col],
                                            Vp[(kv0 + 1) * 72 + col]);
                __half2 b1 = __halves2half2(Vp[(kv0 + 8) * 72 + col],
                                            Vp[(kv0 + 9) * 72 + col]);
                uint32_t bf[2];
                bf[0] = h2_bits(b0);
                bf[1] = h2_bits(b1);
                mma_f16(oacc[dt], pf, bf);
            }
        }
        __syncthreads();
    }

    // ---- epilogue ----
    const float inv0 = 1.0f / l0;
    const float inv1 = 1.0f / l1;
    const int q0row = qbase + wid * 16 + g;
    const int q1row = q0row + 8;
    const bool v0 = (q0row < L);
    const bool v1 = (q1row < L);
    float* o0 = out + ((size_t)(b * SEQ + q0row)) * EMB + h * DHEAD;
    float* o1 = out + ((size_t)(b * SEQ + q1row)) * EMB + h * DHEAD;
#pragma unroll
    for (int dt = 0; dt < 8; dt++) {
        const int col = dt * 8 + 2 * c;
        float2 r0 = v0 ? make_float2(oacc[dt][0] * inv0, oacc[dt][1] * inv0)
                       : make_float2(0.f, 0.f);
        float2 r1 = v1 ? make_float2(oacc[dt][2] * inv1, oacc[dt][3] * inv1)
                       : make_float2(0.f, 0.f);
        *(float2*)(o0 + col) = r0;
        *(float2*)(o1 + col) = r1;
    }
}

// ---------------------------------------------------------------------------
// Launch
// ---------------------------------------------------------------------------
extern "C" void kernel_launch(void* const* d_in, const int* in_sizes, int n_in,
                              void* d_out, int out_size) {
    const float* x = nullptr;
    const int*   l = nullptr;
    const float* W = nullptr;
    const float* bias = nullptr;
    for (int i = 0; i < n_in; i++) {
        switch (in_sizes[i]) {
            case 8388608: x    = (const float*)d_in[i]; break;
            case 8:       l    = (const int*)d_in[i];   break;
            case 3145728: W    = (const float*)d_in[i]; break;
            case 3072:    bias = (const float*)d_in[i]; break;
            default: break;
        }
    }
    float* out = (float*)d_out;

    __half *xh = nullptr, *wh = nullptr, *qkvh = nullptr;
    cudaGetSymbolAddress((void**)&xh,   g_xh);
    cudaGetSymbolAddress((void**)&wh,   g_wh);
    cudaGetSymbolAddress((void**)&qkvh, g_qkvh);

    static bool attr_set = false;
    if (!attr_set) {
        cudaFuncSetAttribute(qkv_gemm_h,
                             cudaFuncAttributeMaxDynamicSharedMemorySize,
                             SMEM_GEMM_TOTAL);
        cudaFuncSetAttribute(attn_h,
                             cudaFuncAttributeMaxDynamicSharedMemorySize,
                             ATT_SMEM);
        attr_set = true;
    }

    // fp32 -> fp16 conversion of x and W
    {
        const int n4x = (BATCH * SEQ * EMB) / 4;   // 2097152
        const int n4w = (E3 * EMB) / 4;            // 786432
        to_half_kernel<<<n4x / 256, 256>>>((const float4*)x, (uint2*)xh, n4x);
        to_half_kernel<<<n4w / 256, 256>>>((const float4*)W, (uint2*)wh, n4w);
    }

    dim3 gg(E3 / BN, (BATCH * SEQ) / BM);     // (24, 32)
    qkv_gemm_h<<<gg, 512, SMEM_GEMM_TOTAL>>>(xh, wh, bias, qkvh);

    dim3 ga(SEQ / 64, NHEAD, BATCH);          // (16, 16, 8)
    attn_h<<<ga, 128, ATT_SMEM>>>(qkvh, l, out);
}

// round 8
// speedup vs baseline: 6.8145x; 1.2113x over previous
#include <cuda_runtime.h>
#include <cuda_fp16.h>
#include <cstdint>
#include <cstddef>

// Problem constants
#define BATCH 8
#define SEQ   1024
#define EMB   1024
#define NHEAD 16
#define DHEAD 64
#define E3    3072   // 3*EMB

// Scratch: fp16 copies of x and W, fp16 QKV projection output
__device__ __half g_xh[(size_t)BATCH * SEQ * EMB];
__device__ __half g_wh[(size_t)E3 * EMB];
__device__ __half g_qkvh[(size_t)BATCH * SEQ * E3];

// ---------------------------------------------------------------------------
// Helpers
// ---------------------------------------------------------------------------
__device__ __forceinline__ uint32_t h2_bits(__half2 h) {
    return *reinterpret_cast<uint32_t*>(&h);
}

__device__ __forceinline__ __half2 bits_h2(uint32_t u) {
    return *reinterpret_cast<__half2*>(&u);
}

__device__ __forceinline__ uint32_t smem_u32(const void* p) {
    uint32_t a;
    asm("{ .reg .u64 t; cvta.to.shared.u64 t, %1; cvt.u32.u64 %0, t; }"
        : "=r"(a) : "l"(p));
    return a;
}

__device__ __forceinline__ void cp16(uint32_t dst, const void* src) {
    asm volatile("cp.async.cg.shared.global [%0], [%1], 16;"
                 :: "r"(dst), "l"(src) : "memory");
}

// mma.sync m16n8k16 f16 with fp32 accum: D += A*B, row.col
__device__ __forceinline__ void mma_f16(float* d, const uint32_t* a, const uint32_t* b) {
    asm volatile(
        "mma.sync.aligned.m16n8k16.row.col.f32.f16.f16.f32 "
        "{%0,%1,%2,%3}, {%4,%5,%6,%7}, {%8,%9}, {%0,%1,%2,%3};"
        : "+f"(d[0]), "+f"(d[1]), "+f"(d[2]), "+f"(d[3])
        : "r"(a[0]), "r"(a[1]), "r"(a[2]), "r"(a[3]),
          "r"(b[0]), "r"(b[1]));
}

__device__ __forceinline__ void ldsm_x4(uint32_t* r, uint32_t addr) {
    asm volatile("ldmatrix.sync.aligned.m8n8.x4.shared.b16 {%0,%1,%2,%3}, [%4];"
                 : "=r"(r[0]), "=r"(r[1]), "=r"(r[2]), "=r"(r[3]) : "r"(addr));
}

__device__ __forceinline__ void ldsm_x4_t(uint32_t* r, uint32_t addr) {
    asm volatile("ldmatrix.sync.aligned.m8n8.x4.trans.shared.b16 {%0,%1,%2,%3}, [%4];"
                 : "=r"(r[0]), "=r"(r[1]), "=r"(r[2]), "=r"(r[3]) : "r"(addr));
}

__device__ __forceinline__ void ldsm_x2(uint32_t* r, uint32_t addr) {
    asm volatile("ldmatrix.sync.aligned.m8n8.x2.shared.b16 {%0,%1}, [%2];"
                 : "=r"(r[0]), "=r"(r[1]) : "r"(addr));
}

// ---------------------------------------------------------------------------
// Robust length read (int64 vs int32 l buffer)
// ---------------------------------------------------------------------------
__device__ __forceinline__ int get_len(const int* __restrict__ p, int b) {
    bool is64 = ((p[1] | p[3] | p[5] | p[7]) == 0);
    return is64 ? p[2 * b] : p[b];
}

// ---------------------------------------------------------------------------
// Pre-pass: fp32 -> fp16
// ---------------------------------------------------------------------------
__global__ void to_half_kernel(const float4* __restrict__ in,
                               uint2* __restrict__ out, int n4) {
    int i = blockIdx.x * blockDim.x + threadIdx.x;
    if (i < n4) {
        float4 v = in[i];
        uint2 o;
        o.x = h2_bits(__floats2half2_rn(v.x, v.y));
        o.y = h2_bits(__floats2half2_rn(v.z, v.w));
        out[i] = o;
    }
}

// ---------------------------------------------------------------------------
// Kernel A: QKV projection GEMM (mma.sync f16, fp32 accum)
// Skips M-blocks entirely beyond the batch's valid length: those qkv rows are
// never semantically consumed (stale-but-finite values are fine downstream).
// CTA 256x128, BK=32 halves, 3-stage cp.async, 512 threads, warp 64x32.
// ---------------------------------------------------------------------------
#define BM 256
#define BN 128
#define BKH 32
#define NKI (1024 / BKH)    // 32
#define NSTG 3
#define RPH 40
#define STG_HALVES ((BM + BN) * RPH)                  // 15360
#define SMEM_GEMM_TOTAL (NSTG * STG_HALVES * 2)       // 92160 bytes

__global__ __launch_bounds__(512) void qkv_gemm_h(
    const __half* __restrict__ A,
    const __half* __restrict__ W,
    const float* __restrict__ bias,
    const int* __restrict__ lens,
    __half* __restrict__ C)
{
    extern __shared__ __half smh[];

    const int bm = blockIdx.y * BM;
    // Skip CTAs whose whole 256-row block is beyond this batch's valid length
    {
        const int lb = get_len(lens, bm >> 10);
        if ((bm & 1023) >= lb) return;
    }

    const int tid  = threadIdx.x;
    const int wid  = tid >> 5;
    const int lane = tid & 31;
    const int g = lane >> 2;
    const int c = lane & 3;
    const int wm = wid >> 2;
    const int wn = wid & 3;
    const int bn = blockIdx.x * BN;

    float acc[4][4][4];
#pragma unroll
    for (int mi = 0; mi < 4; mi++)
#pragma unroll
        for (int ni = 0; ni < 4; ni++)
#pragma unroll
            for (int r = 0; r < 4; r++) acc[mi][ni][r] = 0.f;

    const uint32_t sm_u = smem_u32(smh);

    const uint32_t a_base = ((uint32_t)((wm * 64 + (lane & 15)) * RPH
                                        + ((lane >> 4) << 3))) * 2;
    const uint32_t b_base = ((uint32_t)((BM + wn * 32 + (lane & 7)) * RPH
                                        + (((lane >> 3) & 1) << 3))) * 2;

#define LOAD_STAGE(kt, s)                                                      \
    {                                                                          \
        const int kof = (kt) * BKH;                                            \
        const uint32_t dst = sm_u + (uint32_t)(s) * (STG_HALVES * 2);          \
        _Pragma("unroll")                                                      \
        for (int f = 0; f < 3; f++) {                                          \
            const int idx = f * 512 + tid;                                     \
            if (idx < 1024) {                                                  \
                const int row = idx >> 2;                                      \
                const int ch  = (idx & 3) << 3;                                \
                cp16(dst + (row * RPH + ch) * 2,                               \
                     A + (size_t)(bm + row) * 1024 + kof + ch);                \
            } else {                                                           \
                const int gdx = idx - 1024;                                    \
                const int row = gdx >> 2;                                      \
                const int ch  = (gdx & 3) << 3;                                \
                cp16(dst + ((BM + row) * RPH + ch) * 2,                        \
                     W + (size_t)(bn + row) * 1024 + kof + ch);                \
            }                                                                  \
        }                                                                      \
        asm volatile("cp.async.commit_group;" ::: "memory");                   \
    }

    LOAD_STAGE(0, 0);
    LOAD_STAGE(1, 1);

#pragma unroll 1
    for (int kt = 0; kt < NKI; kt++) {
        asm volatile("cp.async.wait_group 1;" ::: "memory");
        __syncthreads();

        if (kt + 2 < NKI) {
            const int s2 = (kt + 2) % NSTG;
            LOAD_STAGE(kt + 2, s2);
        }

        const uint32_t stg = sm_u + (uint32_t)(kt % NSTG) * (STG_HALVES * 2);
        const uint32_t aB = stg + a_base;
        const uint32_t bB = stg + b_base;

#pragma unroll
        for (int kk = 0; kk < 2; kk++) {
            uint32_t af[4][4], bf[4][2];
#pragma unroll
            for (int mi = 0; mi < 4; mi++)
                ldsm_x4(af[mi], aB + (uint32_t)((mi * 16 * RPH + kk * 16) * 2));
#pragma unroll
            for (int ni = 0; ni < 4; ni++)
                ldsm_x2(bf[ni], bB + (uint32_t)((ni * 8 * RPH + kk * 16) * 2));
#pragma unroll
            for (int mi = 0; mi < 4; mi++)
#pragma unroll
                for (int ni = 0; ni < 4; ni++)
                    mma_f16(acc[mi][ni], af[mi], bf[ni]);
        }
    }

#pragma unroll
    for (int mi = 0; mi < 4; mi++) {
        const int r0 = bm + wm * 64 + mi * 16 + g;
#pragma unroll
        for (int ni = 0; ni < 4; ni++) {
            const int col = bn + wn * 32 + ni * 8 + c * 2;
            const float bx = __ldg(bias + col);
            const float by = __ldg(bias + col + 1);
            __half2 v0 = __floats2half2_rn(acc[mi][ni][0] + bx, acc[mi][ni][1] + by);
            __half2 v1 = __floats2half2_rn(acc[mi][ni][2] + bx, acc[mi][ni][3] + by);
            *(__half2*)(C + (size_t)r0 * E3 + col) = v0;
            *(__half2*)(C + (size_t)(r0 + 8) * E3 + col) = v1;
        }
    }
}

// ---------------------------------------------------------------------------
// Kernel B: flash attention, fp16 operands, fp32 accum/softmax.
// All fragments via ldmatrix: Q/P x4 (A layout), K x4 (B pairs),
// V x4.trans (transposed B pairs — no scalar assembly).
// Block: 128 threads (4 warps) per (b, h, 64-row q tile). Bc = 64.
// ---------------------------------------------------------------------------
#define ATT_TH 4608                       // 64*72 halves
#define ATT_SMEM (5 * ATT_TH * 2)         // 46080 bytes

__global__ __launch_bounds__(128) void attn_h(
    const __half* __restrict__ qkv,
    const int* __restrict__ lens,
    float* __restrict__ out)
{
    extern __shared__ __half smh[];
    __half* QP = smh + 4 * ATT_TH;

    const int tid  = threadIdx.x;
    const int wid  = tid >> 5;
    const int lane = tid & 31;
    const int g = lane >> 2;
    const int c = lane & 3;

    const int qt = blockIdx.x;
    const int h  = blockIdx.y;
    const int b  = blockIdx.z;
    const int L  = get_len(lens, b);
    const int qbase = qt * 64;

    float* outp = out + ((size_t)(b * SEQ + qbase)) * EMB + h * DHEAD;

    if (qbase >= L) {
        float4 z = make_float4(0.f, 0.f, 0.f, 0.f);
#pragma unroll
        for (int t = 0; t < 8; t++) {
            int idx = t * 128 + tid;
            int row = idx >> 4, c4 = (idx & 15) << 2;
            *(float4*)(outp + (size_t)row * EMB + c4) = z;
        }
        return;
    }

    // load Q tile (64 rows x 64 halves) into QP
    {
        const __half* qgp = qkv + ((size_t)(b * SEQ + qbase)) * E3 + h * DHEAD;
#pragma unroll
        for (int t = 0; t < 4; t++) {
            int idx = t * 128 + tid;
            int row = idx >> 3, ch = (idx & 7) << 3;
            *(uint4*)&QP[row * 72 + ch] = *(const uint4*)(qgp + (size_t)row * E3 + ch);
        }
    }
    __syncthreads();

    const uint32_t sm_u = smem_u32(smh);
    const uint32_t QP_u = smem_u32(QP);
    const uint32_t Pw_u = QP_u + (uint32_t)(wid * 16 * 72) * 2;

    // A-layout lane offset (Q/P x4, V x4.trans): row=(lane&15), col8=(lane>>4)
    const uint32_t a_off = ((uint32_t)((lane & 15) * 72 + ((lane >> 4) << 3))) * 2;
    // B-layout lane offset (K x4): row=(lane&7)+((lane>>4)<<3), col8=((lane>>3)&1)
    const uint32_t k_off = ((uint32_t)(((lane & 7) + ((lane >> 4) << 3)) * 72
                                       + (((lane >> 3) & 1) << 3))) * 2;

    // Q fragments via ldmatrix, scaled by 1/32 (exact in fp16)
    uint32_t qf[4][4];
    {
        const __half2 qs = __float2half2_rn(0.03125f);
#pragma unroll
        for (int kk = 0; kk < 4; kk++) {
            ldsm_x4(qf[kk], Pw_u + a_off + kk * 32);
#pragma unroll
            for (int r = 0; r < 4; r++)
                qf[kk][r] = h2_bits(__hmul2(bits_h2(qf[kk][r]), qs));
        }
    }

    const int ktmax = min(qt, (L - 1) >> 6);

#define KV_LOAD(kt, buf)                                                        \
    {                                                                           \
        const __half* kgp = qkv + ((size_t)(b * SEQ + (kt) * 64)) * E3          \
                            + EMB + h * DHEAD;                                  \
        const uint32_t dK = sm_u + (uint32_t)((buf) * ATT_TH) * 2;              \
        const uint32_t dV = sm_u + (uint32_t)((2 + (buf)) * ATT_TH) * 2;        \
        _Pragma("unroll")                                                       \
        for (int t = 0; t < 8; t++) {                                           \
            int idx = t * 128 + tid;                                            \
            if (idx < 512) {                                                    \
                int row = idx >> 3, ch = (idx & 7) << 3;                        \
                cp16(dK + (row * 72 + ch) * 2, kgp + (size_t)row * E3 + ch);    \
            } else {                                                            \
                int jdx = idx - 512;                                            \
                int row = jdx >> 3, ch = (jdx & 7) << 3;                        \
                cp16(dV + (row * 72 + ch) * 2,                                  \
                     kgp + (size_t)row * E3 + EMB + ch);                        \
            }                                                                   \
        }                                                                       \
        asm volatile("cp.async.commit_group;" ::: "memory");                    \
    }

    KV_LOAD(0, 0);

    float m0 = -1e30f, m1 = -1e30f, l0 = 0.f, l1 = 0.f;
    float oacc[8][4];
#pragma unroll
    for (int dt = 0; dt < 8; dt++)
#pragma unroll
        for (int r = 0; r < 4; r++) oacc[dt][r] = 0.f;

    __half* Pw = QP + (wid * 16) * 72;

#pragma unroll 1
    for (int kt = 0; kt <= ktmax; kt++) {
        if (kt < ktmax) KV_LOAD(kt + 1, (kt + 1) & 1);
        if (kt < ktmax) asm volatile("cp.async.wait_group 1;" ::: "memory");
        else            asm volatile("cp.async.wait_group 0;" ::: "memory");
        __syncthreads();

        const uint32_t Kp_u = sm_u + (uint32_t)((kt & 1) * ATT_TH) * 2;
        const uint32_t Vp_u = sm_u + (uint32_t)((2 + (kt & 1)) * ATT_TH) * 2;

        // ---- S = Q @ K^T  (K fragments: ldmatrix.x4 = 2 B-fragments) ----
        float sacc[8][4];
#pragma unroll
        for (int nt = 0; nt < 8; nt++)
#pragma unroll
            for (int r = 0; r < 4; r++) sacc[nt][r] = 0.f;

#pragma unroll
        for (int kk = 0; kk < 4; kk++) {
#pragma unroll
            for (int nt2 = 0; nt2 < 4; nt2++) {
                uint32_t bf4[4];
                ldsm_x4(bf4, Kp_u + k_off + (uint32_t)(nt2 * 2304 + kk * 32));
                mma_f16(sacc[2 * nt2],     qf[kk], bf4);
                mma_f16(sacc[2 * nt2 + 1], qf[kk], bf4 + 2);
            }
        }

        // ---- causal mask (diagonal tile only) ----
        if (kt == qt) {
            const int lr0 = wid * 16 + g;
            const int lr1 = lr0 + 8;
#pragma unroll
            for (int nt = 0; nt < 8; nt++) {
                const int col0 = nt * 8 + 2 * c;
                if (col0 > lr0)     sacc[nt][0] = -1e30f;
                if (col0 + 1 > lr0) sacc[nt][1] = -1e30f;
                if (col0 > lr1)     sacc[nt][2] = -1e30f;
                if (col0 + 1 > lr1) sacc[nt][3] = -1e30f;
            }
        }

        // ---- online softmax ----
        float tm0 = -1e30f, tm1 = -1e30f;
#pragma unroll
        for (int nt = 0; nt < 8; nt++) {
            tm0 = fmaxf(tm0, fmaxf(sacc[nt][0], sacc[nt][1]));
            tm1 = fmaxf(tm1, fmaxf(sacc[nt][2], sacc[nt][3]));
        }
        tm0 = fmaxf(tm0, __shfl_xor_sync(0xFFFFFFFF, tm0, 1));
        tm0 = fmaxf(tm0, __shfl_xor_sync(0xFFFFFFFF, tm0, 2));
        tm1 = fmaxf(tm1, __shfl_xor_sync(0xFFFFFFFF, tm1, 1));
        tm1 = fmaxf(tm1, __shfl_xor_sync(0xFFFFFFFF, tm1, 2));

        const float nm0 = fmaxf(m0, tm0);
        const float nm1 = fmaxf(m1, tm1);
        const float cor0 = __expf(m0 - nm0);
        const float cor1 = __expf(m1 - nm1);
        l0 *= cor0; l1 *= cor1;
#pragma unroll
        for (int dt = 0; dt < 8; dt++) {
            oacc[dt][0] *= cor0; oacc[dt][1] *= cor0;
            oacc[dt][2] *= cor1; oacc[dt][3] *= cor1;
        }

        float ps0 = 0.f, ps1 = 0.f;
#pragma unroll
        for (int nt = 0; nt < 8; nt++) {
            const float p0 = __expf(sacc[nt][0] - nm0);
            const float p1 = __expf(sacc[nt][1] - nm0);
            const float p2 = __expf(sacc[nt][2] - nm1);
            const float p3 = __expf(sacc[nt][3] - nm1);
            ps0 += p0 + p1; ps1 += p2 + p3;
            *(__half2*)&Pw[g * 72 + nt * 8 + 2 * c]       = __floats2half2_rn(p0, p1);
            *(__half2*)&Pw[(g + 8) * 72 + nt * 8 + 2 * c] = __floats2half2_rn(p2, p3);
        }
        ps0 += __shfl_xor_sync(0xFFFFFFFF, ps0, 1);
        ps0 += __shfl_xor_sync(0xFFFFFFFF, ps0, 2);
        ps1 += __shfl_xor_sync(0xFFFFFFFF, ps1, 1);
        ps1 += __shfl_xor_sync(0xFFFFFFFF, ps1, 2);
        l0 += ps0; l1 += ps1;
        m0 = nm0; m1 = nm1;
        __syncwarp();

        // ---- O += P @ V ----
        // P: ldmatrix.x4 (A layout); V: ldmatrix.x4.trans = 2 B-fragments
#pragma unroll
        for (int kk = 0; kk < 4; kk++) {
            uint32_t pf[4];
            ldsm_x4(pf, Pw_u + a_off + kk * 32);
#pragma unroll
            for (int dtp = 0; dtp < 4; dtp++) {
                uint32_t bf4[4];
                ldsm_x4_t(bf4, Vp_u + a_off + (uint32_t)(kk * 2304 + dtp * 32));
                mma_f16(oacc[2 * dtp],     pf, bf4);
                mma_f16(oacc[2 * dtp + 1], pf, bf4 + 2);
            }
        }
        __syncthreads();
    }

    // ---- epilogue ----
    const float inv0 = 1.0f / l0;
    const float inv1 = 1.0f / l1;
    const int q0row = qbase + wid * 16 + g;
    const int q1row = q0row + 8;
    const bool v0 = (q0row < L);
    const bool v1 = (q1row < L);
    float* o0 = out + ((size_t)(b * SEQ + q0row)) * EMB + h * DHEAD;
    float* o1 = out + ((size_t)(b * SEQ + q1row)) * EMB + h * DHEAD;
#pragma unroll
    for (int dt = 0; dt < 8; dt++) {
        const int col = dt * 8 + 2 * c;
        float2 r0 = v0 ? make_float2(oacc[dt][0] * inv0, oacc[dt][1] * inv0)
                       : make_float2(0.f, 0.f);
        float2 r1 = v1 ? make_float2(oacc[dt][2] * inv1, oacc[dt][3] * inv1)
                       : make_float2(0.f, 0.f);
        *(float2*)(o0 + col) = r0;
        *(float2*)(o1 + col) = r1;
    }
}

// ---------------------------------------------------------------------------
// Launch
// ---------------------------------------------------------------------------
extern "C" void kernel_launch(void* const* d_in, const int* in_sizes, int n_in,
                              void* d_out, int out_size) {
    const float* x = nullptr;
    const int*   l = nullptr;
    const float* W = nullptr;
    const float* bias = nullptr;
    for (int i = 0; i < n_in; i++) {
        switch (in_sizes[i]) {
            case 8388608: x    = (const float*)d_in[i]; break;
            case 8:       l    = (const int*)d_in[i];   break;
            case 3145728: W    = (const float*)d_in[i]; break;
            case 3072:    bias = (const float*)d_in[i]; break;
            default: break;
        }
    }
    float* out = (float*)d_out;

    __half *xh = nullptr, *wh = nullptr, *qkvh = nullptr;
    cudaGetSymbolAddress((void**)&xh,   g_xh);
    cudaGetSymbolAddress((void**)&wh,   g_wh);
    cudaGetSymbolAddress((void**)&qkvh, g_qkvh);

    static bool attr_set = false;
    if (!attr_set) {
        cudaFuncSetAttribute(qkv_gemm_h,
                             cudaFuncAttributeMaxDynamicSharedMemorySize,
                             SMEM_GEMM_TOTAL);
        cudaFuncSetAttribute(attn_h,
                             cudaFuncAttributeMaxDynamicSharedMemorySize,
                             ATT_SMEM);
        attr_set = true;
    }

    // fp32 -> fp16 conversion of x and W
    {
        const int n4x = (BATCH * SEQ * EMB) / 4;   // 2097152
        const int n4w = (E3 * EMB) / 4;            // 786432
        to_half_kernel<<<n4x / 256, 256>>>((const float4*)x, (uint2*)xh, n4x);
        to_half_kernel<<<n4w / 256, 256>>>((const float4*)W, (uint2*)wh, n4w);
    }

    dim3 gg(E3 / BN, (BATCH * SEQ) / BM);     // (24, 32)
    qkv_gemm_h<<<gg, 512, SMEM_GEMM_TOTAL>>>(xh, wh, bias, l, qkvh);

    dim3 ga(SEQ / 64, NHEAD, BATCH);          // (16, 16, 8)
    attn_h<<<ga, 128, ATT_SMEM>>>(qkvh, l, out);
}